// round 1
// baseline (speedup 1.0000x reference)
#include <cuda_runtime.h>

#define DM   1024
#define SEQL 2048
#define NB   2
#define NH   16
#define HD   64
#define NTOK 4096   // NB*SEQL

// Scratch (device globals: allocation-free per harness rules)
__device__ float g_q [NTOK * DM];
__device__ float g_k [NTOK * DM];
__device__ float g_v [NTOK * DM];
__device__ float g_qr[NTOK * DM];   // [B,H,S,64] after RoPE
__device__ float g_kr[NTOK * DM];   // [B,H,S,64] after RoPE
__device__ float g_at[NTOK * DM];   // attention output, [B,S,D]

// ---------------------------------------------------------------------------
// SGEMM-NT: C[N,M] = A[N,K] * B[M,K]^T, K = DM = 1024, all row-major fp32.
// 128x128 tile, BK=16, 256 threads, 8x8 register tile per thread.
// ---------------------------------------------------------------------------
__global__ __launch_bounds__(256) void sgemm_nt(const float* __restrict__ A,
                                                const float* __restrict__ B,
                                                float* __restrict__ C) {
    __shared__ float As[16][132];   // padded: store-phase bank spread
    __shared__ float Bs[16][132];

    const int tid = threadIdx.x;
    const int tx  = tid & 15;
    const int ty  = tid >> 4;
    const int m0  = blockIdx.x * 128;
    const int n0  = blockIdx.y * 128;

    float acc[8][8];
#pragma unroll
    for (int i = 0; i < 8; i++)
#pragma unroll
        for (int j = 0; j < 8; j++) acc[i][j] = 0.f;

    for (int k0 = 0; k0 < DM; k0 += 16) {
#pragma unroll
        for (int l = 0; l < 2; l++) {
            int f  = tid + l * 256;        // float4 id within 128x16 tile
            int r  = f >> 2;
            int c4 = (f & 3) << 2;
            float4 a = *(const float4*)(A + (size_t)(n0 + r) * DM + k0 + c4);
            As[c4 + 0][r] = a.x; As[c4 + 1][r] = a.y;
            As[c4 + 2][r] = a.z; As[c4 + 3][r] = a.w;
            float4 b = *(const float4*)(B + (size_t)(m0 + r) * DM + k0 + c4);
            Bs[c4 + 0][r] = b.x; Bs[c4 + 1][r] = b.y;
            Bs[c4 + 2][r] = b.z; Bs[c4 + 3][r] = b.w;
        }
        __syncthreads();
#pragma unroll
        for (int kk = 0; kk < 16; kk++) {
            float4 a0 = *(float4*)&As[kk][ty * 4];
            float4 a1 = *(float4*)&As[kk][ty * 4 + 64];
            float4 b0 = *(float4*)&Bs[kk][tx * 4];
            float4 b1 = *(float4*)&Bs[kk][tx * 4 + 64];
            float av[8] = {a0.x, a0.y, a0.z, a0.w, a1.x, a1.y, a1.z, a1.w};
            float bv[8] = {b0.x, b0.y, b0.z, b0.w, b1.x, b1.y, b1.z, b1.w};
#pragma unroll
            for (int i = 0; i < 8; i++)
#pragma unroll
                for (int j = 0; j < 8; j++)
                    acc[i][j] = fmaf(av[i], bv[j], acc[i][j]);
        }
        __syncthreads();
    }

#pragma unroll
    for (int i = 0; i < 8; i++) {
        int row = n0 + ty * 4 + (i & 3) + ((i >> 2) << 6);
        float* cp = C + (size_t)row * DM + m0;
        *(float4*)(cp + tx * 4)      = make_float4(acc[i][0], acc[i][1], acc[i][2], acc[i][3]);
        *(float4*)(cp + tx * 4 + 64) = make_float4(acc[i][4], acc[i][5], acc[i][6], acc[i][7]);
    }
}

// ---------------------------------------------------------------------------
// RoPE + transpose to [B,H,S,64] for q and k.
// ---------------------------------------------------------------------------
__global__ __launch_bounds__(256) void rope_kernel(const float* __restrict__ cosT,
                                                   const float* __restrict__ sinT) {
    int idx = blockIdx.x * blockDim.x + threadIdx.x;   // < NTOK*DM
    int n = idx >> 10;        // token id (b*SEQL + s)
    int c = idx & 1023;       // channel
    int b = n >> 11;
    int s = n & 2047;
    int h  = c >> 6;
    int dd = c & 63;

    float cs = cosT[(s << 6) + dd];
    float sn = sinT[(s << 6) + dd];

    int base   = (n << 10) + (h << 6);
    int rotoff = (dd < 32) ? dd + 32 : dd - 32;
    float sgn  = (dd < 32) ? -1.f : 1.f;

    float qv   = g_q[idx];
    float qrot = sgn * g_q[base + rotoff];
    float kv   = g_k[idx];
    float krot = sgn * g_k[base + rotoff];

    int out = ((((b << 4) + h) * SEQL + s) << 6) + dd;
    g_qr[out] = qv * cs + qrot * sn;
    g_kr[out] = kv * cs + krot * sn;
}

// ---------------------------------------------------------------------------
// Flash attention fp32, causal. 64x64 tiles, 256 threads (16x16, 4x4/thread).
// smem: Qs[64][64] | KsT[64][68] (aliased as Ps after scores) | Vs[64][64]
// ---------------------------------------------------------------------------
__global__ __launch_bounds__(256) void flash_kernel() {
    extern __shared__ float sm[];
    float* Qs  = sm;                       // 4096 floats
    float* KsT = sm + 4096;                // 64*68 = 4352 floats (also Ps)
    float* Vs  = sm + 4096 + 64 * 68;      // 4096 floats

    const int tid = threadIdx.x;
    const int tx  = tid & 15;
    const int ty  = tid >> 4;
    const int iy0 = ty * 4;

    const int qi = blockIdx.x;             // q tile (0..31)
    const int bh = blockIdx.y;             // b*16+h (0..31)
    const int b  = bh >> 4;
    const int h  = bh & 15;
    const int q0 = qi * 64;

    const float* Qg    = g_qr + ((size_t)bh * SEQL + q0) * HD;
    const float* Kbase = g_kr + (size_t)bh * SEQL * HD;
    const float* Vbase = g_v + (size_t)b * SEQL * DM + h * HD;

    // load Q tile
#pragma unroll
    for (int l = 0; l < 4; l++) {
        int f  = tid + l * 256;            // 1024 float4s
        int r  = f >> 4;
        int c4 = (f & 15) << 2;
        *(float4*)&Qs[r * 64 + c4] = *(const float4*)(Qg + r * 64 + c4);
    }

    float m[4], lsum[4], o[4][4];
#pragma unroll
    for (int i = 0; i < 4; i++) {
        m[i] = -1e30f; lsum[i] = 0.f;
#pragma unroll
        for (int j = 0; j < 4; j++) o[i][j] = 0.f;
    }

    const float scale = 0.125f;   // 1/sqrt(64)
    const unsigned FULL = 0xffffffffu;

    for (int kt = 0; kt <= qi; kt++) {
        const int k0 = kt * 64;
        // load K (transposed) and V tiles
#pragma unroll
        for (int l = 0; l < 4; l++) {
            int f  = tid + l * 256;
            int r  = f >> 4;
            int c4 = (f & 15) << 2;
            float4 kv = *(const float4*)(Kbase + (size_t)(k0 + r) * HD + c4);
            KsT[(c4 + 0) * 68 + r] = kv.x;
            KsT[(c4 + 1) * 68 + r] = kv.y;
            KsT[(c4 + 2) * 68 + r] = kv.z;
            KsT[(c4 + 3) * 68 + r] = kv.w;
            *(float4*)&Vs[r * 64 + c4] =
                *(const float4*)(Vbase + (size_t)(k0 + r) * DM + c4);
        }
        __syncthreads();

        // S = Q K^T
        float s4[4][4];
#pragma unroll
        for (int i = 0; i < 4; i++)
#pragma unroll
            for (int j = 0; j < 4; j++) s4[i][j] = 0.f;

#pragma unroll 8
        for (int dd = 0; dd < 64; dd++) {
            float4 kv = *(float4*)&KsT[dd * 68 + tx * 4];
            float q0v = Qs[(iy0 + 0) * 64 + dd];
            float q1v = Qs[(iy0 + 1) * 64 + dd];
            float q2v = Qs[(iy0 + 2) * 64 + dd];
            float q3v = Qs[(iy0 + 3) * 64 + dd];
            s4[0][0] = fmaf(q0v, kv.x, s4[0][0]); s4[0][1] = fmaf(q0v, kv.y, s4[0][1]);
            s4[0][2] = fmaf(q0v, kv.z, s4[0][2]); s4[0][3] = fmaf(q0v, kv.w, s4[0][3]);
            s4[1][0] = fmaf(q1v, kv.x, s4[1][0]); s4[1][1] = fmaf(q1v, kv.y, s4[1][1]);
            s4[1][2] = fmaf(q1v, kv.z, s4[1][2]); s4[1][3] = fmaf(q1v, kv.w, s4[1][3]);
            s4[2][0] = fmaf(q2v, kv.x, s4[2][0]); s4[2][1] = fmaf(q2v, kv.y, s4[2][1]);
            s4[2][2] = fmaf(q2v, kv.z, s4[2][2]); s4[2][3] = fmaf(q2v, kv.w, s4[2][3]);
            s4[3][0] = fmaf(q3v, kv.x, s4[3][0]); s4[3][1] = fmaf(q3v, kv.y, s4[3][1]);
            s4[3][2] = fmaf(q3v, kv.z, s4[3][2]); s4[3][3] = fmaf(q3v, kv.w, s4[3][3]);
        }

        // scale + causal mask (only diagonal tile needs masking)
        const bool diag = (kt == qi);
#pragma unroll
        for (int i = 0; i < 4; i++)
#pragma unroll
            for (int j = 0; j < 4; j++) {
                float sv = s4[i][j] * scale;
                if (diag && (k0 + tx * 4 + j) > (q0 + iy0 + i)) sv = -1e30f;
                s4[i][j] = sv;
            }

        // online softmax update (row groups = 16 contiguous lanes)
        float p[4][4];
#pragma unroll
        for (int i = 0; i < 4; i++) {
            float mv = fmaxf(fmaxf(s4[i][0], s4[i][1]), fmaxf(s4[i][2], s4[i][3]));
#pragma unroll
            for (int off = 8; off >= 1; off >>= 1)
                mv = fmaxf(mv, __shfl_xor_sync(FULL, mv, off));
            float mn    = fmaxf(m[i], mv);
            float alpha = __expf(m[i] - mn);
            m[i] = mn;
            float rs = 0.f;
#pragma unroll
            for (int j = 0; j < 4; j++) {
                p[i][j] = __expf(s4[i][j] - mn);
                rs += p[i][j];
            }
#pragma unroll
            for (int off = 8; off >= 1; off >>= 1)
                rs += __shfl_xor_sync(FULL, rs, off);
            lsum[i] = lsum[i] * alpha + rs;
#pragma unroll
            for (int j = 0; j < 4; j++) o[i][j] *= alpha;
        }
        __syncthreads();   // everyone done reading KsT

        float* Ps = KsT;   // alias: P tile, stride 68
#pragma unroll
        for (int i = 0; i < 4; i++)
#pragma unroll
            for (int j = 0; j < 4; j++)
                Ps[(iy0 + i) * 68 + tx * 4 + j] = p[i][j];
        __syncthreads();   // P ready

        // O += P V
#pragma unroll 8
        for (int j = 0; j < 64; j++) {
            float4 vv = *(float4*)&Vs[j * 64 + tx * 4];
            float p0 = Ps[(iy0 + 0) * 68 + j];
            float p1 = Ps[(iy0 + 1) * 68 + j];
            float p2 = Ps[(iy0 + 2) * 68 + j];
            float p3 = Ps[(iy0 + 3) * 68 + j];
            o[0][0] = fmaf(p0, vv.x, o[0][0]); o[0][1] = fmaf(p0, vv.y, o[0][1]);
            o[0][2] = fmaf(p0, vv.z, o[0][2]); o[0][3] = fmaf(p0, vv.w, o[0][3]);
            o[1][0] = fmaf(p1, vv.x, o[1][0]); o[1][1] = fmaf(p1, vv.y, o[1][1]);
            o[1][2] = fmaf(p1, vv.z, o[1][2]); o[1][3] = fmaf(p1, vv.w, o[1][3]);
            o[2][0] = fmaf(p2, vv.x, o[2][0]); o[2][1] = fmaf(p2, vv.y, o[2][1]);
            o[2][2] = fmaf(p2, vv.z, o[2][2]); o[2][3] = fmaf(p2, vv.w, o[2][3]);
            o[3][0] = fmaf(p3, vv.x, o[3][0]); o[3][1] = fmaf(p3, vv.y, o[3][1]);
            o[3][2] = fmaf(p3, vv.z, o[3][2]); o[3][3] = fmaf(p3, vv.w, o[3][3]);
        }
        __syncthreads();   // done with Ps/Vs before next load
    }

    // write O / l  -> g_at in [B,S,D] layout
#pragma unroll
    for (int i = 0; i < 4; i++) {
        float inv = 1.f / lsum[i];
        int row = q0 + iy0 + i;
        float4 r = make_float4(o[i][0] * inv, o[i][1] * inv,
                               o[i][2] * inv, o[i][3] * inv);
        *(float4*)(g_at + ((size_t)(b * SEQL + row)) * DM + h * HD + tx * 4) = r;
    }
}

// ---------------------------------------------------------------------------
extern "C" void kernel_launch(void* const* d_in, const int* in_sizes, int n_in,
                              void* d_out, int out_size) {
    const float* x    = (const float*)d_in[0];
    const float* cosT = (const float*)d_in[1];
    const float* sinT = (const float*)d_in[2];
    const float* Wq   = (const float*)d_in[3];
    const float* Wk   = (const float*)d_in[4];
    const float* Wv   = (const float*)d_in[5];
    const float* Wo   = (const float*)d_in[6];
    float* out = (float*)d_out;

    float *qp, *kp, *vp, *atp;
    cudaGetSymbolAddress((void**)&qp,  g_q);
    cudaGetSymbolAddress((void**)&kp,  g_k);
    cudaGetSymbolAddress((void**)&vp,  g_v);
    cudaGetSymbolAddress((void**)&atp, g_at);

    dim3 ggrid(DM / 128, NTOK / 128);     // (8, 32)
    sgemm_nt<<<ggrid, 256>>>(x, Wq, qp);
    sgemm_nt<<<ggrid, 256>>>(x, Wk, kp);
    sgemm_nt<<<ggrid, 256>>>(x, Wv, vp);

    rope_kernel<<<(NTOK * DM) / 256, 256>>>(cosT, sinT);

    const int FLASH_SMEM = (4096 + 64 * 68 + 4096) * 4;   // 50176 B
    cudaFuncSetAttribute(flash_kernel,
                         cudaFuncAttributeMaxDynamicSharedMemorySize, FLASH_SMEM);
    flash_kernel<<<dim3(SEQL / 64, NB * NH), 256, FLASH_SMEM>>>();

    sgemm_nt<<<ggrid, 256>>>(atp, Wo, out);
}

// round 3
// speedup vs baseline: 1.3897x; 1.3897x over previous
#include <cuda_runtime.h>
#include <cuda_bf16.h>
#include <cstdint>

#define DM   1024
#define SEQL 2048
#define NB   2
#define NH   16
#define HD   64
#define NTOK 4096   // NB*SEQL

// ------------------------- scratch (device globals) -------------------------
__device__ float g_q [NTOK * DM];
__device__ float g_k [NTOK * DM];
__device__ float g_v [NTOK * DM];
__device__ float g_qr[NTOK * DM];   // [B,H,S,64] after RoPE
__device__ float g_kr[NTOK * DM];   // [B,H,S,64] after RoPE
__device__ float g_at[NTOK * DM];   // attention output, [B,S,D]

__device__ __nv_bfloat16 g_xh[NTOK * DM], g_xl[NTOK * DM];      // x split
__device__ __nv_bfloat16 g_wh[4 * DM * DM], g_wl[4 * DM * DM];  // Wq,Wk,Wv,Wo split
__device__ __nv_bfloat16 g_ah[NTOK * DM], g_al[NTOK * DM];      // attn-out split

// ------------------------------ PTX helpers --------------------------------
__device__ __forceinline__ uint32_t smem_u32(const void* p) {
    uint32_t a;
    asm("{ .reg .u64 t; cvta.to.shared.u64 t, %1; cvt.u32.u64 %0, t; }"
        : "=r"(a) : "l"(p));
    return a;
}
__device__ __forceinline__ void cpa16(uint32_t dst, const void* src) {
    asm volatile("cp.async.cg.shared.global [%0], [%1], 16;\n" :: "r"(dst), "l"(src));
}
#define CP_COMMIT() asm volatile("cp.async.commit_group;\n" ::: "memory")

__device__ __forceinline__ void ldsm4(uint32_t* r, uint32_t addr) {
    asm volatile("ldmatrix.sync.aligned.m8n8.x4.shared.b16 {%0,%1,%2,%3}, [%4];"
                 : "=r"(r[0]), "=r"(r[1]), "=r"(r[2]), "=r"(r[3]) : "r"(addr));
}
__device__ __forceinline__ void ldsm2(uint32_t* r, uint32_t addr) {
    asm volatile("ldmatrix.sync.aligned.m8n8.x2.shared.b16 {%0,%1}, [%2];"
                 : "=r"(r[0]), "=r"(r[1]) : "r"(addr));
}
__device__ __forceinline__ void mma_bf16(float* d, const uint32_t* a, const uint32_t* b) {
    asm volatile("mma.sync.aligned.m16n8k16.row.col.f32.bf16.bf16.f32 "
                 "{%0,%1,%2,%3}, {%4,%5,%6,%7}, {%8,%9}, {%0,%1,%2,%3};"
                 : "+f"(d[0]), "+f"(d[1]), "+f"(d[2]), "+f"(d[3])
                 : "r"(a[0]), "r"(a[1]), "r"(a[2]), "r"(a[3]), "r"(b[0]), "r"(b[1]));
}

// ---------------------------------------------------------------------------
// fp32 -> (hi, lo) bf16 split
// ---------------------------------------------------------------------------
__global__ __launch_bounds__(256) void split_k(const float* __restrict__ s,
                                               __nv_bfloat16* __restrict__ h,
                                               __nv_bfloat16* __restrict__ l, int n) {
    int i = blockIdx.x * 256 + threadIdx.x;
    if (i >= n) return;
    float v = s[i];
    __nv_bfloat16 hb = __float2bfloat16(v);
    h[i] = hb;
    l[i] = __float2bfloat16(v - __bfloat162float(hb));
}

// ---------------------------------------------------------------------------
// mma.sync split-bf16 GEMM: C[M,N] = A[M,K] * B[N,K]^T, fp32 accumulate.
// CTA tile 128x128, BK=32, 2-stage cp.async, 8 warps (2x4), warp tile 64x32.
// smem rows padded to 40 bf16 (80B) -> conflict-free LDSM phases.
// ---------------------------------------------------------------------------
#define LDA 40
#define MAT_BYTES (128 * LDA * 2)            // 10240
#define STAGE_BYTES (4 * MAT_BYTES)          // Ah | Al | Bh | Bl = 40960
#define GEMM_SMEM (2 * STAGE_BYTES)          // 81920
#define NCH (DM / 32)                        // 32 k-chunks

__device__ __forceinline__ void load_stage(const __nv_bfloat16* Ah, const __nv_bfloat16* Al,
                                           const __nv_bfloat16* Bh, const __nv_bfloat16* Bl,
                                           uint32_t sbase, int m0, int n0, int k0, int tid) {
#pragma unroll
    for (int l = 0; l < 2; l++) {
        int f   = tid + l * 256;             // 0..511
        int r   = f >> 2;                    // row 0..127
        int cb  = (f & 3) << 4;              // byte col in 64B row
        int ce  = (f & 3) << 3;              // elem col
        uint32_t d = sbase + r * (LDA * 2) + cb;
        size_t offA = (size_t)(m0 + r) * DM + k0 + ce;
        size_t offB = (size_t)(n0 + r) * DM + k0 + ce;
        cpa16(d,                 Ah + offA);
        cpa16(d + MAT_BYTES,     Al + offA);
        cpa16(d + 2 * MAT_BYTES, Bh + offB);
        cpa16(d + 3 * MAT_BYTES, Bl + offB);
    }
    CP_COMMIT();
}

__global__ __launch_bounds__(256)
void gemm_bf16x2(const __nv_bfloat16* __restrict__ Ah, const __nv_bfloat16* __restrict__ Al,
                 const __nv_bfloat16* __restrict__ Bh, const __nv_bfloat16* __restrict__ Bl,
                 float* __restrict__ C) {
    extern __shared__ char sm[];
    uint32_t sb = smem_u32(sm);

    const int tid  = threadIdx.x;
    const int wid  = tid >> 5;
    const int lane = tid & 31;
    const int wm   = (wid & 1) * 64;         // warp m offset
    const int wn   = (wid >> 1) * 32;        // warp n offset
    const int n0   = blockIdx.x * 128;
    const int m0   = blockIdx.y * 128;

    float acc[4][4][4];
#pragma unroll
    for (int i = 0; i < 4; i++)
#pragma unroll
        for (int j = 0; j < 4; j++)
#pragma unroll
            for (int c = 0; c < 4; c++) acc[i][j][c] = 0.f;

    // prologue
    load_stage(Ah, Al, Bh, Bl, sb, m0, n0, 0, tid);
    load_stage(Ah, Al, Bh, Bl, sb + STAGE_BYTES, m0, n0, 32, tid);

    // per-thread fragment address components
    const int a_row = wm + (lane & 15);                    // + mt*16
    const int a_col = (lane >> 4) << 3;                    // + ks*16
    const int b_row = wn + (lane & 7);                     // + nt*8
    const int b_col = ((lane >> 3) & 1) << 3;              // + ks*16

    for (int i = 0; i < NCH; i++) {
        uint32_t base = sb + (i & 1) * STAGE_BYTES;
        if (i < NCH - 2) asm volatile("cp.async.wait_group 1;\n" ::: "memory");
        else             asm volatile("cp.async.wait_group 0;\n" ::: "memory");
        __syncthreads();

        uint32_t sAh = base, sAl = base + MAT_BYTES;
        uint32_t sBh = base + 2 * MAT_BYTES, sBl = base + 3 * MAT_BYTES;

#pragma unroll
        for (int ks = 0; ks < 2; ks++) {
            const int kc = ks * 16;
            uint32_t bh[4][2], bl[4][2];
#pragma unroll
            for (int nt = 0; nt < 4; nt++) {
                uint32_t boff = (uint32_t)((b_row + nt * 8) * LDA + kc + b_col) * 2;
                ldsm2(bh[nt], sBh + boff);
                ldsm2(bl[nt], sBl + boff);
            }
#pragma unroll
            for (int mt = 0; mt < 4; mt++) {
                uint32_t aoff = (uint32_t)((a_row + mt * 16) * LDA + kc + a_col) * 2;
                uint32_t ah[4], al[4];
                ldsm4(ah, sAh + aoff);
                ldsm4(al, sAl + aoff);
#pragma unroll
                for (int nt = 0; nt < 4; nt++) {
                    mma_bf16(acc[mt][nt], ah, bh[nt]);
                    mma_bf16(acc[mt][nt], ah, bl[nt]);
                    mma_bf16(acc[mt][nt], al, bh[nt]);
                }
            }
        }
        __syncthreads();   // everyone done reading this stage
        if (i + 2 < NCH)
            load_stage(Ah, Al, Bh, Bl, base, m0, n0, (i + 2) * 32, tid);
    }

    // epilogue: fragment layout -> C
    const int er = lane >> 2;
    const int ec = (lane & 3) * 2;
#pragma unroll
    for (int mt = 0; mt < 4; mt++)
#pragma unroll
        for (int nt = 0; nt < 4; nt++) {
            int row = m0 + wm + mt * 16 + er;
            int col = n0 + wn + nt * 8 + ec;
            *(float2*)(C + (size_t)row * DM + col) =
                make_float2(acc[mt][nt][0], acc[mt][nt][1]);
            *(float2*)(C + (size_t)(row + 8) * DM + col) =
                make_float2(acc[mt][nt][2], acc[mt][nt][3]);
        }
}

// ---------------------------------------------------------------------------
// RoPE + transpose to [B,H,S,64] for q and k.
// ---------------------------------------------------------------------------
__global__ __launch_bounds__(256) void rope_kernel(const float* __restrict__ cosT,
                                                   const float* __restrict__ sinT) {
    int idx = blockIdx.x * blockDim.x + threadIdx.x;   // < NTOK*DM
    int n = idx >> 10;        // token id (b*SEQL + s)
    int c = idx & 1023;       // channel
    int b = n >> 11;
    int s = n & 2047;
    int h  = c >> 6;
    int dd = c & 63;

    float cs = cosT[(s << 6) + dd];
    float sn = sinT[(s << 6) + dd];

    int base   = (n << 10) + (h << 6);
    int rotoff = (dd < 32) ? dd + 32 : dd - 32;
    float sgn  = (dd < 32) ? -1.f : 1.f;

    float qv   = g_q[idx];
    float qrot = sgn * g_q[base + rotoff];
    float kv   = g_k[idx];
    float krot = sgn * g_k[base + rotoff];

    int out = ((((b << 4) + h) * SEQL + s) << 6) + dd;
    g_qr[out] = qv * cs + qrot * sn;
    g_kr[out] = kv * cs + krot * sn;
}

// ---------------------------------------------------------------------------
// Flash attention fp32, causal. 64x64 tiles, 256 threads (16x16, 4x4/thread).
// ---------------------------------------------------------------------------
__global__ __launch_bounds__(256) void flash_kernel() {
    extern __shared__ float smf[];
    float* Qs  = smf;                       // 4096 floats
    float* KsT = smf + 4096;                // 64*68 (also Ps)
    float* Vs  = smf + 4096 + 64 * 68;      // 4096 floats

    const int tid = threadIdx.x;
    const int tx  = tid & 15;
    const int ty  = tid >> 4;
    const int iy0 = ty * 4;

    const int qi = blockIdx.x;
    const int bh = blockIdx.y;
    const int b  = bh >> 4;
    const int h  = bh & 15;
    const int q0 = qi * 64;

    const float* Qg    = g_qr + ((size_t)bh * SEQL + q0) * HD;
    const float* Kbase = g_kr + (size_t)bh * SEQL * HD;
    const float* Vbase = g_v + (size_t)b * SEQL * DM + h * HD;

#pragma unroll
    for (int l = 0; l < 4; l++) {
        int f  = tid + l * 256;
        int r  = f >> 4;
        int c4 = (f & 15) << 2;
        *(float4*)&Qs[r * 64 + c4] = *(const float4*)(Qg + r * 64 + c4);
    }

    float m[4], lsum[4], o[4][4];
#pragma unroll
    for (int i = 0; i < 4; i++) {
        m[i] = -1e30f; lsum[i] = 0.f;
#pragma unroll
        for (int j = 0; j < 4; j++) o[i][j] = 0.f;
    }

    const float scale = 0.125f;
    const unsigned FULL = 0xffffffffu;

    for (int kt = 0; kt <= qi; kt++) {
        const int k0 = kt * 64;
#pragma unroll
        for (int l = 0; l < 4; l++) {
            int f  = tid + l * 256;
            int r  = f >> 4;
            int c4 = (f & 15) << 2;
            float4 kv = *(const float4*)(Kbase + (size_t)(k0 + r) * HD + c4);
            KsT[(c4 + 0) * 68 + r] = kv.x;
            KsT[(c4 + 1) * 68 + r] = kv.y;
            KsT[(c4 + 2) * 68 + r] = kv.z;
            KsT[(c4 + 3) * 68 + r] = kv.w;
            *(float4*)&Vs[r * 64 + c4] =
                *(const float4*)(Vbase + (size_t)(k0 + r) * DM + c4);
        }
        __syncthreads();

        float s4[4][4];
#pragma unroll
        for (int i = 0; i < 4; i++)
#pragma unroll
            for (int j = 0; j < 4; j++) s4[i][j] = 0.f;

#pragma unroll 8
        for (int dd = 0; dd < 64; dd++) {
            float4 kv = *(float4*)&KsT[dd * 68 + tx * 4];
            float q0v = Qs[(iy0 + 0) * 64 + dd];
            float q1v = Qs[(iy0 + 1) * 64 + dd];
            float q2v = Qs[(iy0 + 2) * 64 + dd];
            float q3v = Qs[(iy0 + 3) * 64 + dd];
            s4[0][0] = fmaf(q0v, kv.x, s4[0][0]); s4[0][1] = fmaf(q0v, kv.y, s4[0][1]);
            s4[0][2] = fmaf(q0v, kv.z, s4[0][2]); s4[0][3] = fmaf(q0v, kv.w, s4[0][3]);
            s4[1][0] = fmaf(q1v, kv.x, s4[1][0]); s4[1][1] = fmaf(q1v, kv.y, s4[1][1]);
            s4[1][2] = fmaf(q1v, kv.z, s4[1][2]); s4[1][3] = fmaf(q1v, kv.w, s4[1][3]);
            s4[2][0] = fmaf(q2v, kv.x, s4[2][0]); s4[2][1] = fmaf(q2v, kv.y, s4[2][1]);
            s4[2][2] = fmaf(q2v, kv.z, s4[2][2]); s4[2][3] = fmaf(q2v, kv.w, s4[2][3]);
            s4[3][0] = fmaf(q3v, kv.x, s4[3][0]); s4[3][1] = fmaf(q3v, kv.y, s4[3][1]);
            s4[3][2] = fmaf(q3v, kv.z, s4[3][2]); s4[3][3] = fmaf(q3v, kv.w, s4[3][3]);
        }

        const bool diag = (kt == qi);
#pragma unroll
        for (int i = 0; i < 4; i++)
#pragma unroll
            for (int j = 0; j < 4; j++) {
                float sv = s4[i][j] * scale;
                if (diag && (k0 + tx * 4 + j) > (q0 + iy0 + i)) sv = -1e30f;
                s4[i][j] = sv;
            }

        float p[4][4];
#pragma unroll
        for (int i = 0; i < 4; i++) {
            float mv = fmaxf(fmaxf(s4[i][0], s4[i][1]), fmaxf(s4[i][2], s4[i][3]));
#pragma unroll
            for (int off = 8; off >= 1; off >>= 1)
                mv = fmaxf(mv, __shfl_xor_sync(FULL, mv, off));
            float mn    = fmaxf(m[i], mv);
            float alpha = __expf(m[i] - mn);
            m[i] = mn;
            float rs = 0.f;
#pragma unroll
            for (int j = 0; j < 4; j++) {
                p[i][j] = __expf(s4[i][j] - mn);
                rs += p[i][j];
            }
#pragma unroll
            for (int off = 8; off >= 1; off >>= 1)
                rs += __shfl_xor_sync(FULL, rs, off);
            lsum[i] = lsum[i] * alpha + rs;
#pragma unroll
            for (int j = 0; j < 4; j++) o[i][j] *= alpha;
        }
        __syncthreads();

        float* Ps = KsT;
#pragma unroll
        for (int i = 0; i < 4; i++)
#pragma unroll
            for (int j = 0; j < 4; j++)
                Ps[(iy0 + i) * 68 + tx * 4 + j] = p[i][j];
        __syncthreads();

#pragma unroll 8
        for (int j = 0; j < 64; j++) {
            float4 vv = *(float4*)&Vs[j * 64 + tx * 4];
            float p0 = Ps[(iy0 + 0) * 68 + j];
            float p1 = Ps[(iy0 + 1) * 68 + j];
            float p2 = Ps[(iy0 + 2) * 68 + j];
            float p3 = Ps[(iy0 + 3) * 68 + j];
            o[0][0] = fmaf(p0, vv.x, o[0][0]); o[0][1] = fmaf(p0, vv.y, o[0][1]);
            o[0][2] = fmaf(p0, vv.z, o[0][2]); o[0][3] = fmaf(p0, vv.w, o[0][3]);
            o[1][0] = fmaf(p1, vv.x, o[1][0]); o[1][1] = fmaf(p1, vv.y, o[1][1]);
            o[1][2] = fmaf(p1, vv.z, o[1][2]); o[1][3] = fmaf(p1, vv.w, o[1][3]);
            o[2][0] = fmaf(p2, vv.x, o[2][0]); o[2][1] = fmaf(p2, vv.y, o[2][1]);
            o[2][2] = fmaf(p2, vv.z, o[2][2]); o[2][3] = fmaf(p2, vv.w, o[2][3]);
            o[3][0] = fmaf(p3, vv.x, o[3][0]); o[3][1] = fmaf(p3, vv.y, o[3][1]);
            o[3][2] = fmaf(p3, vv.z, o[3][2]); o[3][3] = fmaf(p3, vv.w, o[3][3]);
        }
        __syncthreads();
    }

#pragma unroll
    for (int i = 0; i < 4; i++) {
        float inv = 1.f / lsum[i];
        int row = q0 + iy0 + i;
        float4 r = make_float4(o[i][0] * inv, o[i][1] * inv,
                               o[i][2] * inv, o[i][3] * inv);
        *(float4*)(g_at + ((size_t)(b * SEQL + row)) * DM + h * HD + tx * 4) = r;
    }
}

// ---------------------------------------------------------------------------
extern "C" void kernel_launch(void* const* d_in, const int* in_sizes, int n_in,
                              void* d_out, int out_size) {
    const float* x    = (const float*)d_in[0];
    const float* cosT = (const float*)d_in[1];
    const float* sinT = (const float*)d_in[2];
    const float* W[4] = {(const float*)d_in[3], (const float*)d_in[4],
                         (const float*)d_in[5], (const float*)d_in[6]};
    float* out = (float*)d_out;

    float *qp, *kp, *vp, *atp;
    cudaGetSymbolAddress((void**)&qp,  g_q);
    cudaGetSymbolAddress((void**)&kp,  g_k);
    cudaGetSymbolAddress((void**)&vp,  g_v);
    cudaGetSymbolAddress((void**)&atp, g_at);
    __nv_bfloat16 *xh, *xl, *wh, *wl, *ah, *al;
    cudaGetSymbolAddress((void**)&xh, g_xh);
    cudaGetSymbolAddress((void**)&xl, g_xl);
    cudaGetSymbolAddress((void**)&wh, g_wh);
    cudaGetSymbolAddress((void**)&wl, g_wl);
    cudaGetSymbolAddress((void**)&ah, g_ah);
    cudaGetSymbolAddress((void**)&al, g_al);

    static bool attr_done = false;
    if (!attr_done) {
        cudaFuncSetAttribute(gemm_bf16x2,
                             cudaFuncAttributeMaxDynamicSharedMemorySize, GEMM_SMEM);
        cudaFuncSetAttribute(flash_kernel,
                             cudaFuncAttributeMaxDynamicSharedMemorySize,
                             (4096 + 64 * 68 + 4096) * 4);
        attr_done = true;
    }

    // splits
    split_k<<<(NTOK * DM) / 256, 256>>>(x, xh, xl, NTOK * DM);
    for (int i = 0; i < 4; i++)
        split_k<<<(DM * DM) / 256, 256>>>(W[i], wh + (size_t)i * DM * DM,
                                          wl + (size_t)i * DM * DM, DM * DM);

    // projections
    dim3 ggrid(DM / 128, NTOK / 128);     // (8, 32)
    gemm_bf16x2<<<ggrid, 256, GEMM_SMEM>>>(xh, xl, wh + 0 * (size_t)DM * DM,
                                           wl + 0 * (size_t)DM * DM, qp);
    gemm_bf16x2<<<ggrid, 256, GEMM_SMEM>>>(xh, xl, wh + 1 * (size_t)DM * DM,
                                           wl + 1 * (size_t)DM * DM, kp);
    gemm_bf16x2<<<ggrid, 256, GEMM_SMEM>>>(xh, xl, wh + 2 * (size_t)DM * DM,
                                           wl + 2 * (size_t)DM * DM, vp);

    rope_kernel<<<(NTOK * DM) / 256, 256>>>(cosT, sinT);

    const int FLASH_SMEM = (4096 + 64 * 68 + 4096) * 4;
    flash_kernel<<<dim3(SEQL / 64, NB * NH), 256, FLASH_SMEM>>>();

    split_k<<<(NTOK * DM) / 256, 256>>>(atp, ah, al, NTOK * DM);
    gemm_bf16x2<<<ggrid, 256, GEMM_SMEM>>>(ah, al, wh + 3 * (size_t)DM * DM,
                                           wl + 3 * (size_t)DM * DM, out);
}

// round 5
// speedup vs baseline: 1.9455x; 1.3999x over previous
#include <cuda_runtime.h>
#include <cuda_bf16.h>
#include <cstdint>

#define DM   1024
#define SEQL 2048
#define NB   2
#define NH   16
#define HD   64
#define NTOK 4096   // NB*SEQL

// ------------------------- scratch (device globals) -------------------------
__device__ float g_q [NTOK * DM];
__device__ float g_k [NTOK * DM];
__device__ float g_v [NTOK * DM];
__device__ float g_at[NTOK * DM];   // attention output, [B,S,D]

__device__ __nv_bfloat16 g_xh[NTOK * DM], g_xl[NTOK * DM];      // x split
__device__ __nv_bfloat16 g_wh[4 * DM * DM], g_wl[4 * DM * DM];  // Wq,Wk,Wv,Wo split
__device__ __nv_bfloat16 g_ah[NTOK * DM], g_al[NTOK * DM];      // attn-out split
__device__ __nv_bfloat16 g_qrh[NTOK * DM], g_qrl[NTOK * DM];    // RoPE'd Q [B,H,S,64]
__device__ __nv_bfloat16 g_krh[NTOK * DM], g_krl[NTOK * DM];    // RoPE'd K [B,H,S,64]

// ------------------------------ PTX helpers --------------------------------
__device__ __forceinline__ uint32_t smem_u32(const void* p) {
    uint32_t a;
    asm("{ .reg .u64 t; cvta.to.shared.u64 t, %1; cvt.u32.u64 %0, t; }"
        : "=r"(a) : "l"(p));
    return a;
}
__device__ __forceinline__ void cpa16(uint32_t dst, const void* src) {
    asm volatile("cp.async.cg.shared.global [%0], [%1], 16;\n" :: "r"(dst), "l"(src));
}
#define CP_COMMIT() asm volatile("cp.async.commit_group;\n" ::: "memory")

__device__ __forceinline__ void ldsm4(uint32_t* r, uint32_t addr) {
    asm volatile("ldmatrix.sync.aligned.m8n8.x4.shared.b16 {%0,%1,%2,%3}, [%4];"
                 : "=r"(r[0]), "=r"(r[1]), "=r"(r[2]), "=r"(r[3]) : "r"(addr));
}
__device__ __forceinline__ void ldsm2(uint32_t* r, uint32_t addr) {
    asm volatile("ldmatrix.sync.aligned.m8n8.x2.shared.b16 {%0,%1}, [%2];"
                 : "=r"(r[0]), "=r"(r[1]) : "r"(addr));
}
__device__ __forceinline__ void mma_bf16(float* d, const uint32_t* a, const uint32_t* b) {
    asm volatile("mma.sync.aligned.m16n8k16.row.col.f32.bf16.bf16.f32 "
                 "{%0,%1,%2,%3}, {%4,%5,%6,%7}, {%8,%9}, {%0,%1,%2,%3};"
                 : "+f"(d[0]), "+f"(d[1]), "+f"(d[2]), "+f"(d[3])
                 : "r"(a[0]), "r"(a[1]), "r"(a[2]), "r"(a[3]), "r"(b[0]), "r"(b[1]));
}

// FMA-pipe 2^x for x <= 0 (clamped at -126), ~1e-6 accuracy
__device__ __forceinline__ float fexp2(float x) {
    x = fmaxf(x, -126.f);
    float fl = floorf(x);
    float f  = x - fl;
    float p = 1.54035304e-4f;
    p = fmaf(p, f, 1.33335581e-3f);
    p = fmaf(p, f, 9.61812911e-3f);
    p = fmaf(p, f, 5.55041087e-2f);
    p = fmaf(p, f, 2.40226507e-1f);
    p = fmaf(p, f, 6.93147180e-1f);
    p = fmaf(p, f, 1.0f);
    int e = (int)fl;
    return p * __int_as_float((e + 127) << 23);
}

__device__ __forceinline__ uint32_t pk2(float a, float b) {
    __nv_bfloat162 t = __floats2bfloat162_rn(a, b);
    return *(uint32_t*)&t;
}
__device__ __forceinline__ void split2(float a, float b, uint32_t& h, uint32_t& l) {
    __nv_bfloat16 ah = __float2bfloat16(a), bh = __float2bfloat16(b);
    h = pk2((float)ah, (float)bh);  // exact re-pack
    l = pk2(a - (float)ah, b - (float)bh);
}

// ---------------------------------------------------------------------------
// fp32 -> (hi, lo) bf16 split
// ---------------------------------------------------------------------------
__global__ __launch_bounds__(256) void split_k(const float* __restrict__ s,
                                               __nv_bfloat16* __restrict__ h,
                                               __nv_bfloat16* __restrict__ l, int n) {
    int i = blockIdx.x * 256 + threadIdx.x;
    if (i >= n) return;
    float v = s[i];
    __nv_bfloat16 hb = __float2bfloat16(v);
    h[i] = hb;
    l[i] = __float2bfloat16(v - __bfloat162float(hb));
}

// ---------------------------------------------------------------------------
// mma.sync split-bf16 GEMM (verified in R3)
// ---------------------------------------------------------------------------
#define LDA 40
#define MAT_BYTES (128 * LDA * 2)
#define STAGE_BYTES (4 * MAT_BYTES)
#define GEMM_SMEM (2 * STAGE_BYTES)
#define NCH (DM / 32)

__device__ __forceinline__ void load_stage(const __nv_bfloat16* Ah, const __nv_bfloat16* Al,
                                           const __nv_bfloat16* Bh, const __nv_bfloat16* Bl,
                                           uint32_t sbase, int m0, int n0, int k0, int tid) {
#pragma unroll
    for (int l = 0; l < 2; l++) {
        int f   = tid + l * 256;
        int r   = f >> 2;
        int cb  = (f & 3) << 4;
        int ce  = (f & 3) << 3;
        uint32_t d = sbase + r * (LDA * 2) + cb;
        size_t offA = (size_t)(m0 + r) * DM + k0 + ce;
        size_t offB = (size_t)(n0 + r) * DM + k0 + ce;
        cpa16(d,                 Ah + offA);
        cpa16(d + MAT_BYTES,     Al + offA);
        cpa16(d + 2 * MAT_BYTES, Bh + offB);
        cpa16(d + 3 * MAT_BYTES, Bl + offB);
    }
    CP_COMMIT();
}

__global__ __launch_bounds__(256)
void gemm_bf16x2(const __nv_bfloat16* __restrict__ Ah, const __nv_bfloat16* __restrict__ Al,
                 const __nv_bfloat16* __restrict__ Bh, const __nv_bfloat16* __restrict__ Bl,
                 float* __restrict__ C) {
    extern __shared__ char sm[];
    uint32_t sb = smem_u32(sm);

    const int tid  = threadIdx.x;
    const int wid  = tid >> 5;
    const int lane = tid & 31;
    const int wm   = (wid & 1) * 64;
    const int wn   = (wid >> 1) * 32;
    const int n0   = blockIdx.x * 128;
    const int m0   = blockIdx.y * 128;

    float acc[4][4][4];
#pragma unroll
    for (int i = 0; i < 4; i++)
#pragma unroll
        for (int j = 0; j < 4; j++)
#pragma unroll
            for (int c = 0; c < 4; c++) acc[i][j][c] = 0.f;

    load_stage(Ah, Al, Bh, Bl, sb, m0, n0, 0, tid);
    load_stage(Ah, Al, Bh, Bl, sb + STAGE_BYTES, m0, n0, 32, tid);

    const int a_row = wm + (lane & 15);
    const int a_col = (lane >> 4) << 3;
    const int b_row = wn + (lane & 7);
    const int b_col = ((lane >> 3) & 1) << 3;

    for (int i = 0; i < NCH; i++) {
        uint32_t base = sb + (i & 1) * STAGE_BYTES;
        if (i < NCH - 2) asm volatile("cp.async.wait_group 1;\n" ::: "memory");
        else             asm volatile("cp.async.wait_group 0;\n" ::: "memory");
        __syncthreads();

        uint32_t sAh = base, sAl = base + MAT_BYTES;
        uint32_t sBh = base + 2 * MAT_BYTES, sBl = base + 3 * MAT_BYTES;

#pragma unroll
        for (int ks = 0; ks < 2; ks++) {
            const int kc = ks * 16;
            uint32_t bh[4][2], bl[4][2];
#pragma unroll
            for (int nt = 0; nt < 4; nt++) {
                uint32_t boff = (uint32_t)((b_row + nt * 8) * LDA + kc + b_col) * 2;
                ldsm2(bh[nt], sBh + boff);
                ldsm2(bl[nt], sBl + boff);
            }
#pragma unroll
            for (int mt = 0; mt < 4; mt++) {
                uint32_t aoff = (uint32_t)((a_row + mt * 16) * LDA + kc + a_col) * 2;
                uint32_t ah[4], al[4];
                ldsm4(ah, sAh + aoff);
                ldsm4(al, sAl + aoff);
#pragma unroll
                for (int nt = 0; nt < 4; nt++) {
                    mma_bf16(acc[mt][nt], ah, bh[nt]);
                    mma_bf16(acc[mt][nt], ah, bl[nt]);
                    mma_bf16(acc[mt][nt], al, bh[nt]);
                }
            }
        }
        __syncthreads();
        if (i + 2 < NCH)
            load_stage(Ah, Al, Bh, Bl, base, m0, n0, (i + 2) * 32, tid);
    }

    const int er = lane >> 2;
    const int ec = (lane & 3) * 2;
#pragma unroll
    for (int mt = 0; mt < 4; mt++)
#pragma unroll
        for (int nt = 0; nt < 4; nt++) {
            int row = m0 + wm + mt * 16 + er;
            int col = n0 + wn + nt * 8 + ec;
            *(float2*)(C + (size_t)row * DM + col) =
                make_float2(acc[mt][nt][0], acc[mt][nt][1]);
            *(float2*)(C + (size_t)(row + 8) * DM + col) =
                make_float2(acc[mt][nt][2], acc[mt][nt][3]);
        }
}

// ---------------------------------------------------------------------------
// RoPE + transpose to [B,H,S,64], emitting bf16 hi/lo directly.
// ---------------------------------------------------------------------------
__global__ __launch_bounds__(256) void rope_kernel(const float* __restrict__ cosT,
                                                   const float* __restrict__ sinT) {
    int idx = blockIdx.x * blockDim.x + threadIdx.x;
    int n = idx >> 10;
    int c = idx & 1023;
    int b = n >> 11;
    int s = n & 2047;
    int h  = c >> 6;
    int dd = c & 63;

    float cs = cosT[(s << 6) + dd];
    float sn = sinT[(s << 6) + dd];

    int base   = (n << 10) + (h << 6);
    int rotoff = (dd < 32) ? dd + 32 : dd - 32;
    float sgn  = (dd < 32) ? -1.f : 1.f;

    float qv   = g_q[idx];
    float qrot = sgn * g_q[base + rotoff];
    float kv   = g_k[idx];
    float krot = sgn * g_k[base + rotoff];

    int out = ((((b << 4) + h) * SEQL + s) << 6) + dd;
    float qr = qv * cs + qrot * sn;
    float kr = kv * cs + krot * sn;
    __nv_bfloat16 qh = __float2bfloat16(qr);
    __nv_bfloat16 kh = __float2bfloat16(kr);
    g_qrh[out] = qh; g_qrl[out] = __float2bfloat16(qr - __bfloat162float(qh));
    g_krh[out] = kh; g_krl[out] = __float2bfloat16(kr - __bfloat162float(kh));
}

// ---------------------------------------------------------------------------
// Tensor-core flash attention. Q-tile 128, K-tile 64, 8 warps.
// All matmuls = split-bf16 mma.sync (3 terms). Softmax in registers, base-2.
// smem: Qh/Ql[128][72] Kh/Kl[64][72] Vth/Vtl[64][72]  (bf16, pitch 72)
// ---------------------------------------------------------------------------
#define FP 72
#define FL_SMEM ((128 + 128 + 64 + 64 + 64 + 64) * FP * 2)
#define KSC 0.18033688f   // (1/8) * log2(e)

__global__ __launch_bounds__(256) void flash_mma() {
    extern __shared__ char smc[];
    uint32_t sQh = smem_u32(smc);
    uint32_t sQl = sQh + 128 * FP * 2;
    uint32_t sKh = sQl + 128 * FP * 2;
    uint32_t sKl = sKh + 64 * FP * 2;
    uint32_t sVh = sKl + 64 * FP * 2;
    uint32_t sVl = sVh + 64 * FP * 2;
    __nv_bfloat16* Vh = (__nv_bfloat16*)(smc + (128 + 128 + 64 + 64) * FP * 2);
    __nv_bfloat16* Vl = Vh + 64 * FP;

    const int tid  = threadIdx.x;
    const int wid  = tid >> 5;
    const int lane = tid & 31;

    const int qi = blockIdx.x;       // 0..15, q0 = qi*128
    const int bh = blockIdx.y;       // 0..31
    const int b  = bh >> 4;
    const int h  = bh & 15;
    const int q0 = qi * 128;

    const __nv_bfloat16* Qhg = g_qrh + ((size_t)bh * SEQL + q0) * HD;
    const __nv_bfloat16* Qlg = g_qrl + ((size_t)bh * SEQL + q0) * HD;
    const __nv_bfloat16* Khg = g_krh + (size_t)bh * SEQL * HD;
    const __nv_bfloat16* Klg = g_krl + (size_t)bh * SEQL * HD;
    const float* Vg = g_v + (size_t)b * SEQL * DM + h * HD;

    // ---- load Q tile (once) ----
#pragma unroll
    for (int l = 0; l < 4; l++) {
        int f = tid + l * 256;        // 0..1023 = 128 rows x 8 chunks
        int r = f >> 3;
        int c = (f & 7) << 3;
        cpa16(sQh + (r * FP + c) * 2, Qhg + (size_t)r * HD + c);
        cpa16(sQl + (r * FP + c) * 2, Qlg + (size_t)r * HD + c);
    }
    CP_COMMIT();

    // per-lane softmax state (rows: r0 = q0+16*wid+(lane>>2), r1 = r0+8)
    float m0 = -1e30f, m1 = -1e30f, l0 = 0.f, l1 = 0.f;
    float o[8][4];
#pragma unroll
    for (int i = 0; i < 8; i++)
#pragma unroll
        for (int c = 0; c < 4; c++) o[i][c] = 0.f;

    const int row0 = q0 + 16 * wid + (lane >> 2);
    const uint32_t aoffQ = ((16 * wid + (lane & 15)) * FP + ((lane >> 4) << 3)) * 2;
    const uint32_t roffK = ((lane & 15) * FP + ((lane >> 4) << 3)) * 2;

    const int nkt = 2 * qi + 2;
    for (int kt = 0; kt < nkt; kt++) {
        const int k0 = kt * 64;
        // ---- load K tile (cp.async) ----
#pragma unroll
        for (int l = 0; l < 2; l++) {
            int f = tid + l * 256;    // 0..511 = 64 rows x 8 chunks
            int r = f >> 3;
            int c = (f & 7) << 3;
            cpa16(sKh + (r * FP + c) * 2, Khg + (size_t)(k0 + r) * HD + c);
            cpa16(sKl + (r * FP + c) * 2, Klg + (size_t)(k0 + r) * HD + c);
        }
        CP_COMMIT();
        // ---- load V tile fp32, split + transpose into smem ----
#pragma unroll
        for (int l = 0; l < 4; l++) {
            int f   = tid + l * 256;  // 0..1023 = 64 keys x 16 chunks
            int key = f >> 4;
            int c4  = (f & 15) << 2;
            float4 v = *(const float4*)(Vg + (size_t)(k0 + key) * DM + c4);
            float vv[4] = {v.x, v.y, v.z, v.w};
#pragma unroll
            for (int i = 0; i < 4; i++) {
                __nv_bfloat16 hb = __float2bfloat16(vv[i]);
                Vh[(c4 + i) * FP + key] = hb;
                Vl[(c4 + i) * FP + key] = __float2bfloat16(vv[i] - __bfloat162float(hb));
            }
        }
        asm volatile("cp.async.wait_group 0;\n" ::: "memory");
        __syncthreads();

        // ---- S = Q K^T (3-term split) ----
        float s4[8][4];
#pragma unroll
        for (int i = 0; i < 8; i++)
#pragma unroll
            for (int c = 0; c < 4; c++) s4[i][c] = 0.f;

#pragma unroll
        for (int kc = 0; kc < 4; kc++) {
            uint32_t ah[4], al[4];
            ldsm4(ah, sQh + aoffQ + kc * 32);
            ldsm4(al, sQl + aoffQ + kc * 32);
#pragma unroll
            for (int ntp = 0; ntp < 4; ntp++) {
                uint32_t rh[4], rl[4];
                uint32_t off = roffK + ntp * 16 * FP * 2 + kc * 32;
                ldsm4(rh, sKh + off);
                ldsm4(rl, sKl + off);
                uint32_t b0h[2] = {rh[0], rh[2]}, b1h[2] = {rh[1], rh[3]};
                uint32_t b0l[2] = {rl[0], rl[2]}, b1l[2] = {rl[1], rl[3]};
                mma_bf16(s4[2 * ntp],     ah, b0h);
                mma_bf16(s4[2 * ntp],     ah, b0l);
                mma_bf16(s4[2 * ntp],     al, b0h);
                mma_bf16(s4[2 * ntp + 1], ah, b1h);
                mma_bf16(s4[2 * ntp + 1], ah, b1l);
                mma_bf16(s4[2 * ntp + 1], al, b1h);
            }
        }

        // ---- scale (+mask) ----
        const bool masked = (k0 + 63 >= q0);
#pragma unroll
        for (int nt = 0; nt < 8; nt++)
#pragma unroll
            for (int c = 0; c < 4; c++) {
                float sv = s4[nt][c] * KSC;
                if (masked) {
                    int col = k0 + nt * 8 + (lane & 3) * 2 + (c & 1);
                    int row = row0 + ((c >> 1) << 3);
                    if (col > row) sv = -1e30f;
                }
                s4[nt][c] = sv;
            }

        // ---- online softmax (base-2, FMA-pipe exp) ----
        float mx0 = -1e30f, mx1 = -1e30f;
#pragma unroll
        for (int nt = 0; nt < 8; nt++) {
            mx0 = fmaxf(mx0, fmaxf(s4[nt][0], s4[nt][1]));
            mx1 = fmaxf(mx1, fmaxf(s4[nt][2], s4[nt][3]));
        }
        mx0 = fmaxf(mx0, __shfl_xor_sync(0xffffffffu, mx0, 1));
        mx0 = fmaxf(mx0, __shfl_xor_sync(0xffffffffu, mx0, 2));
        mx1 = fmaxf(mx1, __shfl_xor_sync(0xffffffffu, mx1, 1));
        mx1 = fmaxf(mx1, __shfl_xor_sync(0xffffffffu, mx1, 2));
        float mn0 = fmaxf(m0, mx0), mn1 = fmaxf(m1, mx1);
        float al0 = fexp2(m0 - mn0), al1 = fexp2(m1 - mn1);
        m0 = mn0; m1 = mn1;

        float rs0 = 0.f, rs1 = 0.f;
#pragma unroll
        for (int nt = 0; nt < 8; nt++) {
            s4[nt][0] = fexp2(s4[nt][0] - mn0);
            s4[nt][1] = fexp2(s4[nt][1] - mn0);
            s4[nt][2] = fexp2(s4[nt][2] - mn1);
            s4[nt][3] = fexp2(s4[nt][3] - mn1);
            rs0 += s4[nt][0] + s4[nt][1];
            rs1 += s4[nt][2] + s4[nt][3];
        }
        rs0 += __shfl_xor_sync(0xffffffffu, rs0, 1);
        rs0 += __shfl_xor_sync(0xffffffffu, rs0, 2);
        rs1 += __shfl_xor_sync(0xffffffffu, rs1, 1);
        rs1 += __shfl_xor_sync(0xffffffffu, rs1, 2);
        l0 = l0 * al0 + rs0;
        l1 = l1 * al1 + rs1;
#pragma unroll
        for (int nt = 0; nt < 8; nt++) {
            o[nt][0] *= al0; o[nt][1] *= al0;
            o[nt][2] *= al1; o[nt][3] *= al1;
        }

        // ---- O += P V (3-term split) ----
#pragma unroll
        for (int kcp = 0; kcp < 4; kcp++) {
            uint32_t aph[4], apl[4];
            split2(s4[2 * kcp][0],     s4[2 * kcp][1],     aph[0], apl[0]);
            split2(s4[2 * kcp][2],     s4[2 * kcp][3],     aph[1], apl[1]);
            split2(s4[2 * kcp + 1][0], s4[2 * kcp + 1][1], aph[2], apl[2]);
            split2(s4[2 * kcp + 1][2], s4[2 * kcp + 1][3], aph[3], apl[3]);
#pragma unroll
            for (int np = 0; np < 4; np++) {
                uint32_t rh[4], rl[4];
                uint32_t off = roffK + np * 16 * FP * 2 + kcp * 32;
                ldsm4(rh, sVh + off);
                ldsm4(rl, sVl + off);
                uint32_t b0h[2] = {rh[0], rh[2]}, b1h[2] = {rh[1], rh[3]};
                uint32_t b0l[2] = {rl[0], rl[2]}, b1l[2] = {rl[1], rl[3]};
                mma_bf16(o[2 * np],     aph, b0h);
                mma_bf16(o[2 * np],     apl, b0h);
                mma_bf16(o[2 * np],     aph, b0l);
                mma_bf16(o[2 * np + 1], aph, b1h);
                mma_bf16(o[2 * np + 1], apl, b1h);
                mma_bf16(o[2 * np + 1], aph, b1l);
            }
        }
        __syncthreads();   // done reading K/V smem before next tile's stores
    }

    // ---- epilogue: O / l -> g_at [B,S,D] ----
    float inv0 = 1.f / l0, inv1 = 1.f / l1;
#pragma unroll
    for (int nt = 0; nt < 8; nt++) {
        int col = h * HD + nt * 8 + (lane & 3) * 2;
        *(float2*)(g_at + ((size_t)(b * SEQL + row0)) * DM + col) =
            make_float2(o[nt][0] * inv0, o[nt][1] * inv0);
        *(float2*)(g_at + ((size_t)(b * SEQL + row0 + 8)) * DM + col) =
            make_float2(o[nt][2] * inv1, o[nt][3] * inv1);
    }
}

// ---------------------------------------------------------------------------
extern "C" void kernel_launch(void* const* d_in, const int* in_sizes, int n_in,
                              void* d_out, int out_size) {
    const float* x    = (const float*)d_in[0];
    const float* cosT = (const float*)d_in[1];
    const float* sinT = (const float*)d_in[2];
    const float* W[4] = {(const float*)d_in[3], (const float*)d_in[4],
                         (const float*)d_in[5], (const float*)d_in[6]};
    float* out = (float*)d_out;

    float *qp, *kp, *vp, *atp;
    cudaGetSymbolAddress((void**)&qp,  g_q);
    cudaGetSymbolAddress((void**)&kp,  g_k);
    cudaGetSymbolAddress((void**)&vp,  g_v);
    cudaGetSymbolAddress((void**)&atp, g_at);
    __nv_bfloat16 *xh, *xl, *wh, *wl, *ah, *al;
    cudaGetSymbolAddress((void**)&xh, g_xh);
    cudaGetSymbolAddress((void**)&xl, g_xl);
    cudaGetSymbolAddress((void**)&wh, g_wh);
    cudaGetSymbolAddress((void**)&wl, g_wl);
    cudaGetSymbolAddress((void**)&ah, g_ah);
    cudaGetSymbolAddress((void**)&al, g_al);

    // idempotent; no static guards (harness rule)
    cudaFuncSetAttribute(gemm_bf16x2,
                         cudaFuncAttributeMaxDynamicSharedMemorySize, GEMM_SMEM);
    cudaFuncSetAttribute(flash_mma,
                         cudaFuncAttributeMaxDynamicSharedMemorySize, FL_SMEM);

    // splits
    split_k<<<(NTOK * DM) / 256, 256>>>(x, xh, xl, NTOK * DM);
    for (int i = 0; i < 4; i++)
        split_k<<<(DM * DM) / 256, 256>>>(W[i], wh + (size_t)i * DM * DM,
                                          wl + (size_t)i * DM * DM, DM * DM);

    // projections
    dim3 ggrid(DM / 128, NTOK / 128);
    gemm_bf16x2<<<ggrid, 256, GEMM_SMEM>>>(xh, xl, wh + 0 * (size_t)DM * DM,
                                           wl + 0 * (size_t)DM * DM, qp);
    gemm_bf16x2<<<ggrid, 256, GEMM_SMEM>>>(xh, xl, wh + 1 * (size_t)DM * DM,
                                           wl + 1 * (size_t)DM * DM, kp);
    gemm_bf16x2<<<ggrid, 256, GEMM_SMEM>>>(xh, xl, wh + 2 * (size_t)DM * DM,
                                           wl + 2 * (size_t)DM * DM, vp);

    rope_kernel<<<(NTOK * DM) / 256, 256>>>(cosT, sinT);

    flash_mma<<<dim3(SEQL / 128, NB * NH), 256, FL_SMEM>>>();

    split_k<<<(NTOK * DM) / 256, 256>>>(atp, ah, al, NTOK * DM);
    gemm_bf16x2<<<ggrid, 256, GEMM_SMEM>>>(ah, al, wh + 3 * (size_t)DM * DM,
                                           wl + 3 * (size_t)DM * DM, out);
}

// round 8
// speedup vs baseline: 2.2389x; 1.1508x over previous
#include <cuda_runtime.h>
#include <cuda_bf16.h>
#include <cstdint>

#define DM   1024
#define SEQL 2048
#define NB   2
#define NH   16
#define HD   64
#define NTOK 4096   // NB*SEQL

// ------------------------- scratch (device globals) -------------------------
__device__ float g_qkv[NTOK * 3 * DM];                          // fused QKV out
__device__ __nv_bfloat16 g_xh[NTOK * DM], g_xl[NTOK * DM];      // x split
__device__ __nv_bfloat16 g_wh[4 * DM * DM], g_wl[4 * DM * DM];  // Wq,Wk,Wv,Wo split
__device__ __nv_bfloat16 g_ah[NTOK * DM], g_al[NTOK * DM];      // attn-out split
__device__ __nv_bfloat16 g_qrh[NTOK * DM], g_qrl[NTOK * DM];    // RoPE'd Q [B,H,S,64]
__device__ __nv_bfloat16 g_krh[NTOK * DM], g_krl[NTOK * DM];    // RoPE'd K [B,H,S,64]
__device__ __nv_bfloat16 g_vth[NTOK * DM], g_vtl[NTOK * DM];    // V^T [B,H,64,S]

// ------------------------------ PTX helpers --------------------------------
__device__ __forceinline__ uint32_t smem_u32(const void* p) {
    uint32_t a;
    asm("{ .reg .u64 t; cvta.to.shared.u64 t, %1; cvt.u32.u64 %0, t; }"
        : "=r"(a) : "l"(p));
    return a;
}
__device__ __forceinline__ void cpa16(uint32_t dst, const void* src) {
    asm volatile("cp.async.cg.shared.global [%0], [%1], 16;\n" :: "r"(dst), "l"(src));
}
#define CP_COMMIT() asm volatile("cp.async.commit_group;\n" ::: "memory")

__device__ __forceinline__ void ldsm4(uint32_t* r, uint32_t addr) {
    asm volatile("ldmatrix.sync.aligned.m8n8.x4.shared.b16 {%0,%1,%2,%3}, [%4];"
                 : "=r"(r[0]), "=r"(r[1]), "=r"(r[2]), "=r"(r[3]) : "r"(addr));
}
__device__ __forceinline__ void ldsm2(uint32_t* r, uint32_t addr) {
    asm volatile("ldmatrix.sync.aligned.m8n8.x2.shared.b16 {%0,%1}, [%2];"
                 : "=r"(r[0]), "=r"(r[1]) : "r"(addr));
}
__device__ __forceinline__ void mma_bf16(float* d, const uint32_t* a, const uint32_t* b) {
    asm volatile("mma.sync.aligned.m16n8k16.row.col.f32.bf16.bf16.f32 "
                 "{%0,%1,%2,%3}, {%4,%5,%6,%7}, {%8,%9}, {%0,%1,%2,%3};"
                 : "+f"(d[0]), "+f"(d[1]), "+f"(d[2]), "+f"(d[3])
                 : "r"(a[0]), "r"(a[1]), "r"(a[2]), "r"(a[3]), "r"(b[0]), "r"(b[1]));
}

// FMA-pipe 2^x for x <= 0 (clamped), ~1e-6 accuracy
__device__ __forceinline__ float fexp2(float x) {
    x = fmaxf(x, -126.f);
    float fl = floorf(x);
    float f  = x - fl;
    float p = 1.54035304e-4f;
    p = fmaf(p, f, 1.33335581e-3f);
    p = fmaf(p, f, 9.61812911e-3f);
    p = fmaf(p, f, 5.55041087e-2f);
    p = fmaf(p, f, 2.40226507e-1f);
    p = fmaf(p, f, 6.93147180e-1f);
    p = fmaf(p, f, 1.0f);
    int e = (int)fl;
    return p * __int_as_float((e + 127) << 23);
}

__device__ __forceinline__ uint32_t pk2(float a, float b) {
    __nv_bfloat162 t = __floats2bfloat162_rn(a, b);
    return *(uint32_t*)&t;
}
__device__ __forceinline__ void split2(float a, float b, uint32_t& h, uint32_t& l) {
    __nv_bfloat16 ah = __float2bfloat16(a), bh = __float2bfloat16(b);
    h = pk2((float)ah, (float)bh);
    l = pk2(a - (float)ah, b - (float)bh);
}

// ---------------------------------------------------------------------------
// Fused fp32 -> (hi, lo) bf16 split: x (4M elems) + 4 weights (1M each)
// ---------------------------------------------------------------------------
__global__ __launch_bounds__(256) void split_all(const float* __restrict__ x,
                                                 const float* __restrict__ W0,
                                                 const float* __restrict__ W1,
                                                 const float* __restrict__ W2,
                                                 const float* __restrict__ W3) {
    int bid = blockIdx.x;
    const float* src;
    __nv_bfloat16 *dh, *dl;
    int off;
    if (bid < 16384) {                 // x
        src = x; dh = g_xh; dl = g_xl;
        off = bid * 256 + threadIdx.x;
    } else {
        int w = (bid - 16384) >> 12;   // 0..3
        const float* Ws[4] = {W0, W1, W2, W3};
        src = Ws[w];
        dh = g_wh + (size_t)w * DM * DM;
        dl = g_wl + (size_t)w * DM * DM;
        off = ((bid - 16384) & 4095) * 256 + threadIdx.x;
    }
    float v = src[off];
    __nv_bfloat16 hb = __float2bfloat16(v);
    dh[off] = hb;
    dl[off] = __float2bfloat16(v - __bfloat162float(hb));
}

// ---------------------------------------------------------------------------
// mma.sync split-bf16 GEMM: C[M,ldc] = A[M,K] * B[N,K]^T  (ldc = N total)
// ---------------------------------------------------------------------------
#define LDA 40
#define MAT_BYTES (128 * LDA * 2)
#define STAGE_BYTES (4 * MAT_BYTES)
#define GEMM_SMEM (2 * STAGE_BYTES)
#define NCH (DM / 32)

__device__ __forceinline__ void load_stage(const __nv_bfloat16* Ah, const __nv_bfloat16* Al,
                                           const __nv_bfloat16* Bh, const __nv_bfloat16* Bl,
                                           uint32_t sbase, int m0, int n0, int k0, int tid) {
#pragma unroll
    for (int l = 0; l < 2; l++) {
        int f   = tid + l * 256;
        int r   = f >> 2;
        int cb  = (f & 3) << 4;
        int ce  = (f & 3) << 3;
        uint32_t d = sbase + r * (LDA * 2) + cb;
        size_t offA = (size_t)(m0 + r) * DM + k0 + ce;
        size_t offB = (size_t)(n0 + r) * DM + k0 + ce;
        cpa16(d,                 Ah + offA);
        cpa16(d + MAT_BYTES,     Al + offA);
        cpa16(d + 2 * MAT_BYTES, Bh + offB);
        cpa16(d + 3 * MAT_BYTES, Bl + offB);
    }
    CP_COMMIT();
}

__global__ __launch_bounds__(256, 2)
void gemm_bf16x2(const __nv_bfloat16* __restrict__ Ah, const __nv_bfloat16* __restrict__ Al,
                 const __nv_bfloat16* __restrict__ Bh, const __nv_bfloat16* __restrict__ Bl,
                 float* __restrict__ C, int ldc) {
    extern __shared__ char sm[];
    uint32_t sb = smem_u32(sm);

    const int tid  = threadIdx.x;
    const int wid  = tid >> 5;
    const int lane = tid & 31;
    const int wm   = (wid & 1) * 64;
    const int wn   = (wid >> 1) * 32;
    const int n0   = blockIdx.x * 128;
    const int m0   = blockIdx.y * 128;

    float acc[4][4][4];
#pragma unroll
    for (int i = 0; i < 4; i++)
#pragma unroll
        for (int j = 0; j < 4; j++)
#pragma unroll
            for (int c = 0; c < 4; c++) acc[i][j][c] = 0.f;

    load_stage(Ah, Al, Bh, Bl, sb, m0, n0, 0, tid);
    load_stage(Ah, Al, Bh, Bl, sb + STAGE_BYTES, m0, n0, 32, tid);

    const int a_row = wm + (lane & 15);
    const int a_col = (lane >> 4) << 3;
    const int b_row = wn + (lane & 7);
    const int b_col = ((lane >> 3) & 1) << 3;

    for (int i = 0; i < NCH; i++) {
        uint32_t base = sb + (i & 1) * STAGE_BYTES;
        if (i < NCH - 2) asm volatile("cp.async.wait_group 1;\n" ::: "memory");
        else             asm volatile("cp.async.wait_group 0;\n" ::: "memory");
        __syncthreads();

        uint32_t sAh = base, sAl = base + MAT_BYTES;
        uint32_t sBh = base + 2 * MAT_BYTES, sBl = base + 3 * MAT_BYTES;

#pragma unroll
        for (int ks = 0; ks < 2; ks++) {
            const int kc = ks * 16;
            uint32_t bh[4][2], bl[4][2];
#pragma unroll
            for (int nt = 0; nt < 4; nt++) {
                uint32_t boff = (uint32_t)((b_row + nt * 8) * LDA + kc + b_col) * 2;
                ldsm2(bh[nt], sBh + boff);
                ldsm2(bl[nt], sBl + boff);
            }
#pragma unroll
            for (int mt = 0; mt < 4; mt++) {
                uint32_t aoff = (uint32_t)((a_row + mt * 16) * LDA + kc + a_col) * 2;
                uint32_t ah[4], al[4];
                ldsm4(ah, sAh + aoff);
                ldsm4(al, sAl + aoff);
#pragma unroll
                for (int nt = 0; nt < 4; nt++) {
                    mma_bf16(acc[mt][nt], ah, bh[nt]);
                    mma_bf16(acc[mt][nt], ah, bl[nt]);
                    mma_bf16(acc[mt][nt], al, bh[nt]);
                }
            }
        }
        __syncthreads();
        if (i + 2 < NCH)
            load_stage(Ah, Al, Bh, Bl, base, m0, n0, (i + 2) * 32, tid);
    }

    const int er = lane >> 2;
    const int ec = (lane & 3) * 2;
#pragma unroll
    for (int mt = 0; mt < 4; mt++)
#pragma unroll
        for (int nt = 0; nt < 4; nt++) {
            int row = m0 + wm + mt * 16 + er;
            int col = n0 + wn + nt * 8 + ec;
            *(float2*)(C + (size_t)row * ldc + col) =
                make_float2(acc[mt][nt][0], acc[mt][nt][1]);
            *(float2*)(C + (size_t)(row + 8) * ldc + col) =
                make_float2(acc[mt][nt][2], acc[mt][nt][3]);
        }
}

// ---------------------------------------------------------------------------
// RoPE on q,k from g_qkv -> [B,H,S,64] hi/lo bf16
// ---------------------------------------------------------------------------
__global__ __launch_bounds__(256) void rope_kernel(const float* __restrict__ cosT,
                                                   const float* __restrict__ sinT) {
    int idx = blockIdx.x * blockDim.x + threadIdx.x;   // < NTOK*DM
    int n = idx >> 10;
    int c = idx & 1023;
    int b = n >> 11;
    int s = n & 2047;
    int h  = c >> 6;
    int dd = c & 63;

    float cs = cosT[(s << 6) + dd];
    float sn = sinT[(s << 6) + dd];

    size_t base = (size_t)n * 3072 + (h << 6);
    int rotoff = (dd < 32) ? dd + 32 : dd - 32;
    float sgn  = (dd < 32) ? -1.f : 1.f;

    float qv   = g_qkv[base + dd];
    float qrot = sgn * g_qkv[base + rotoff];
    float kv   = g_qkv[base + 1024 + dd];
    float krot = sgn * g_qkv[base + 1024 + rotoff];

    int out = ((((b << 4) + h) * SEQL + s) << 6) + dd;
    float qr = qv * cs + qrot * sn;
    float kr = kv * cs + krot * sn;
    __nv_bfloat16 qh = __float2bfloat16(qr);
    __nv_bfloat16 kh = __float2bfloat16(kr);
    g_qrh[out] = qh; g_qrl[out] = __float2bfloat16(qr - __bfloat162float(qh));
    g_krh[out] = kh; g_krl[out] = __float2bfloat16(kr - __bfloat162float(kh));
}

// ---------------------------------------------------------------------------
// V transpose + split: g_qkv v-part [B,S,H,64] -> g_vth/g_vtl [B,H,64,S]
// ---------------------------------------------------------------------------
__global__ __launch_bounds__(256) void vsplit_t() {
    __shared__ float t[64][65];
    const int tid = threadIdx.x;
    const int bh = blockIdx.y;
    const int b = bh >> 4, h = bh & 15;
    const int s0 = blockIdx.x * 64;

#pragma unroll
    for (int l = 0; l < 16; l++) {
        int f = tid + l * 256;
        int sl = f >> 6, d = f & 63;
        t[sl][d] = g_qkv[(size_t)(b * SEQL + s0 + sl) * 3072 + 2048 + (h << 6) + d];
    }
    __syncthreads();
#pragma unroll
    for (int l = 0; l < 16; l++) {
        int f = tid + l * 256;
        int d = f >> 6, sl = f & 63;
        float v = t[sl][d];
        __nv_bfloat16 hb = __float2bfloat16(v);
        size_t o = ((size_t)bh * 64 + d) * SEQL + s0 + sl;
        g_vth[o] = hb;
        g_vtl[o] = __float2bfloat16(v - __bfloat162float(hb));
    }
}

// ---------------------------------------------------------------------------
// Flash attention, double-buffered cp.async K/V^T, 1 sync per tile.
// Q-tile 128, K-tile 64, 8 warps. Split-bf16 mma (3 terms). Writes hi/lo out.
// ---------------------------------------------------------------------------
#define FP 72
#define FMAT (64 * FP * 2)            // 9216 B per 64x72 bf16 matrix
#define FSTG (4 * FMAT)               // Kh|Kl|Vh|Vl = 36864
#define FQ   (2 * 128 * FP * 2)       // Qh|Ql = 36864
#define FL_SMEM (FQ + 2 * FSTG)       // 110592
#define KSC 0.18033688f               // (1/8) * log2(e)

__global__ __launch_bounds__(256) void flash_mma() {
    extern __shared__ char smc[];
    const uint32_t sQh = smem_u32(smc);
    const uint32_t sQl = sQh + 128 * FP * 2;
    const uint32_t sST = sQh + FQ;     // stage 0 base

    const int tid  = threadIdx.x;
    const int wid  = tid >> 5;
    const int lane = tid & 31;

    const int qi = blockIdx.x;
    const int bh = blockIdx.y;
    const int b  = bh >> 4;
    const int h  = bh & 15;
    const int q0 = qi * 128;

    const __nv_bfloat16* Qhg = g_qrh + ((size_t)bh * SEQL + q0) * HD;
    const __nv_bfloat16* Qlg = g_qrl + ((size_t)bh * SEQL + q0) * HD;
    const __nv_bfloat16* Khg = g_krh + (size_t)bh * SEQL * HD;
    const __nv_bfloat16* Klg = g_krl + (size_t)bh * SEQL * HD;
    const __nv_bfloat16* Vhg = g_vth + (size_t)bh * 64 * SEQL;
    const __nv_bfloat16* Vlg = g_vtl + (size_t)bh * 64 * SEQL;

    // Q load (own group)
#pragma unroll
    for (int l = 0; l < 4; l++) {
        int f = tid + l * 256;
        int r = f >> 3;
        int c = (f & 7) << 3;
        cpa16(sQh + (r * FP + c) * 2, Qhg + (size_t)r * HD + c);
        cpa16(sQl + (r * FP + c) * 2, Qlg + (size_t)r * HD + c);
    }
    CP_COMMIT();

    // tile 0 loads
    {
        const int k0 = 0;
        uint32_t st = sST;
#pragma unroll
        for (int l = 0; l < 2; l++) {
            int f = tid + l * 256;
            int r = f >> 3;
            int c = (f & 7) << 3;
            cpa16(st + (r * FP + c) * 2,            Khg + (size_t)(k0 + r) * HD + c);
            cpa16(st + FMAT + (r * FP + c) * 2,     Klg + (size_t)(k0 + r) * HD + c);
            cpa16(st + 2 * FMAT + (r * FP + c) * 2, Vhg + (size_t)r * SEQL + k0 + c);
            cpa16(st + 3 * FMAT + (r * FP + c) * 2, Vlg + (size_t)r * SEQL + k0 + c);
        }
        CP_COMMIT();
    }

    float m0 = -1e30f, m1 = -1e30f, l0 = 0.f, l1 = 0.f;
    float o[8][4];
#pragma unroll
    for (int i = 0; i < 8; i++)
#pragma unroll
        for (int c = 0; c < 4; c++) o[i][c] = 0.f;

    const int row0 = q0 + 16 * wid + (lane >> 2);
    const uint32_t aoffQ = ((16 * wid + (lane & 15)) * FP + ((lane >> 4) << 3)) * 2;
    const uint32_t roffB = ((lane & 15) * FP + ((lane >> 4) << 3)) * 2;

    const int nkt = 2 * qi + 2;
    for (int kt = 0; kt < nkt; kt++) {
        asm volatile("cp.async.wait_group 0;\n" ::: "memory");
        __syncthreads();

        // prefetch tile kt+1 into other buffer (safe: it was read in kt-1)
        if (kt + 1 < nkt) {
            const int kn = (kt + 1) * 64;
            uint32_t st = sST + ((kt + 1) & 1) * FSTG;
#pragma unroll
            for (int l = 0; l < 2; l++) {
                int f = tid + l * 256;
                int r = f >> 3;
                int c = (f & 7) << 3;
                cpa16(st + (r * FP + c) * 2,            Khg + (size_t)(kn + r) * HD + c);
                cpa16(st + FMAT + (r * FP + c) * 2,     Klg + (size_t)(kn + r) * HD + c);
                cpa16(st + 2 * FMAT + (r * FP + c) * 2, Vhg + (size_t)r * SEQL + kn + c);
                cpa16(st + 3 * FMAT + (r * FP + c) * 2, Vlg + (size_t)r * SEQL + kn + c);
            }
            CP_COMMIT();
        }

        const int k0 = kt * 64;
        const uint32_t st = sST + (kt & 1) * FSTG;
        const uint32_t sKh = st, sKl = st + FMAT;
        const uint32_t sVh = st + 2 * FMAT, sVl = st + 3 * FMAT;

        // ---- S = Q K^T ----
        float s4[8][4];
#pragma unroll
        for (int i = 0; i < 8; i++)
#pragma unroll
            for (int c = 0; c < 4; c++) s4[i][c] = 0.f;

#pragma unroll
        for (int kc = 0; kc < 4; kc++) {
            uint32_t ah[4], al[4];
            ldsm4(ah, sQh + aoffQ + kc * 32);
            ldsm4(al, sQl + aoffQ + kc * 32);
#pragma unroll
            for (int ntp = 0; ntp < 4; ntp++) {
                uint32_t rh[4], rl[4];
                uint32_t off = roffB + ntp * 16 * FP * 2 + kc * 32;
                ldsm4(rh, sKh + off);
                ldsm4(rl, sKl + off);
                uint32_t b0h[2] = {rh[0], rh[2]}, b1h[2] = {rh[1], rh[3]};
                uint32_t b0l[2] = {rl[0], rl[2]}, b1l[2] = {rl[1], rl[3]};
                mma_bf16(s4[2 * ntp],     ah, b0h);
                mma_bf16(s4[2 * ntp],     ah, b0l);
                mma_bf16(s4[2 * ntp],     al, b0h);
                mma_bf16(s4[2 * ntp + 1], ah, b1h);
                mma_bf16(s4[2 * ntp + 1], ah, b1l);
                mma_bf16(s4[2 * ntp + 1], al, b1h);
            }
        }

        // ---- scale + mask ----
        const bool masked = (k0 + 63 >= q0);
#pragma unroll
        for (int nt = 0; nt < 8; nt++)
#pragma unroll
            for (int c = 0; c < 4; c++) {
                float sv = s4[nt][c] * KSC;
                if (masked) {
                    int col = k0 + nt * 8 + (lane & 3) * 2 + (c & 1);
                    int row = row0 + ((c >> 1) << 3);
                    if (col > row) sv = -1e30f;
                }
                s4[nt][c] = sv;
            }

        // ---- online softmax (base-2) ----
        float mx0 = -1e30f, mx1 = -1e30f;
#pragma unroll
        for (int nt = 0; nt < 8; nt++) {
            mx0 = fmaxf(mx0, fmaxf(s4[nt][0], s4[nt][1]));
            mx1 = fmaxf(mx1, fmaxf(s4[nt][2], s4[nt][3]));
        }
        mx0 = fmaxf(mx0, __shfl_xor_sync(0xffffffffu, mx0, 1));
        mx0 = fmaxf(mx0, __shfl_xor_sync(0xffffffffu, mx0, 2));
        mx1 = fmaxf(mx1, __shfl_xor_sync(0xffffffffu, mx1, 1));
        mx1 = fmaxf(mx1, __shfl_xor_sync(0xffffffffu, mx1, 2));
        float mn0 = fmaxf(m0, mx0), mn1 = fmaxf(m1, mx1);
        float al0 = fexp2(m0 - mn0), al1 = fexp2(m1 - mn1);
        m0 = mn0; m1 = mn1;

        float rs0 = 0.f, rs1 = 0.f;
#pragma unroll
        for (int nt = 0; nt < 8; nt++) {
            s4[nt][0] = fexp2(s4[nt][0] - mn0);
            s4[nt][1] = fexp2(s4[nt][1] - mn0);
            s4[nt][2] = fexp2(s4[nt][2] - mn1);
            s4[nt][3] = fexp2(s4[nt][3] - mn1);
            rs0 += s4[nt][0] + s4[nt][1];
            rs1 += s4[nt][2] + s4[nt][3];
        }
        rs0 += __shfl_xor_sync(0xffffffffu, rs0, 1);
        rs0 += __shfl_xor_sync(0xffffffffu, rs0, 2);
        rs1 += __shfl_xor_sync(0xffffffffu, rs1, 1);
        rs1 += __shfl_xor_sync(0xffffffffu, rs1, 2);
        l0 = l0 * al0 + rs0;
        l1 = l1 * al1 + rs1;
#pragma unroll
        for (int nt = 0; nt < 8; nt++) {
            o[nt][0] *= al0; o[nt][1] *= al0;
            o[nt][2] *= al1; o[nt][3] *= al1;
        }

        // ---- O += P V ----
#pragma unroll
        for (int kcp = 0; kcp < 4; kcp++) {
            uint32_t aph[4], apl[4];
            split2(s4[2 * kcp][0],     s4[2 * kcp][1],     aph[0], apl[0]);
            split2(s4[2 * kcp][2],     s4[2 * kcp][3],     aph[1], apl[1]);
            split2(s4[2 * kcp + 1][0], s4[2 * kcp + 1][1], aph[2], apl[2]);
            split2(s4[2 * kcp + 1][2], s4[2 * kcp + 1][3], aph[3], apl[3]);
#pragma unroll
            for (int np = 0; np < 4; np++) {
                uint32_t rh[4], rl[4];
                uint32_t off = roffB + np * 16 * FP * 2 + kcp * 32;
                ldsm4(rh, sVh + off);
                ldsm4(rl, sVl + off);
                uint32_t b0h[2] = {rh[0], rh[2]}, b1h[2] = {rh[1], rh[3]};
                uint32_t b0l[2] = {rl[0], rl[2]}, b1l[2] = {rl[1], rl[3]};
                mma_bf16(o[2 * np],     aph, b0h);
                mma_bf16(o[2 * np],     apl, b0h);
                mma_bf16(o[2 * np],     aph, b0l);
                mma_bf16(o[2 * np + 1], aph, b1h);
                mma_bf16(o[2 * np + 1], apl, b1h);
                mma_bf16(o[2 * np + 1], aph, b1l);
            }
        }
        // no trailing sync: next iteration's sync protects buffer reuse
    }

    // ---- epilogue: normalize, split hi/lo, store ----
    float inv0 = 1.f / l0, inv1 = 1.f / l1;
#pragma unroll
    for (int nt = 0; nt < 8; nt++) {
        int col = (h << 6) + nt * 8 + (lane & 3) * 2;
        uint32_t hi, lo;
        split2(o[nt][0] * inv0, o[nt][1] * inv0, hi, lo);
        *(uint32_t*)(g_ah + (size_t)(b * SEQL + row0) * DM + col) = hi;
        *(uint32_t*)(g_al + (size_t)(b * SEQL + row0) * DM + col) = lo;
        split2(o[nt][2] * inv1, o[nt][3] * inv1, hi, lo);
        *(uint32_t*)(g_ah + (size_t)(b * SEQL + row0 + 8) * DM + col) = hi;
        *(uint32_t*)(g_al + (size_t)(b * SEQL + row0 + 8) * DM + col) = lo;
    }
}

// ---------------------------------------------------------------------------
extern "C" void kernel_launch(void* const* d_in, const int* in_sizes, int n_in,
                              void* d_out, int out_size) {
    const float* x    = (const float*)d_in[0];
    const float* cosT = (const float*)d_in[1];
    const float* sinT = (const float*)d_in[2];
    float* out = (float*)d_out;

    float* qkvp;
    cudaGetSymbolAddress((void**)&qkvp, g_qkv);
    __nv_bfloat16 *xh, *xl, *wh, *wl, *ah, *al;
    cudaGetSymbolAddress((void**)&xh, g_xh);
    cudaGetSymbolAddress((void**)&xl, g_xl);
    cudaGetSymbolAddress((void**)&wh, g_wh);
    cudaGetSymbolAddress((void**)&wl, g_wl);
    cudaGetSymbolAddress((void**)&ah, g_ah);
    cudaGetSymbolAddress((void**)&al, g_al);

    cudaFuncSetAttribute(gemm_bf16x2,
                         cudaFuncAttributeMaxDynamicSharedMemorySize, GEMM_SMEM);
    cudaFuncSetAttribute(flash_mma,
                         cudaFuncAttributeMaxDynamicSharedMemorySize, FL_SMEM);

    // 0: fused split of x + all 4 weights
    split_all<<<32768, 256>>>(x, (const float*)d_in[3], (const float*)d_in[4],
                              (const float*)d_in[5], (const float*)d_in[6]);

    // 1: fused QKV projection (B = [Wq;Wk;Wv] = first 3 MB of split weights)
    gemm_bf16x2<<<dim3(24, 32), 256, GEMM_SMEM>>>(xh, xl, wh, wl, qkvp, 3072);

    // 2: RoPE q,k -> [B,H,S,64] hi/lo
    rope_kernel<<<(NTOK * DM) / 256, 256>>>(cosT, sinT);

    // 3: V transpose + split -> [B,H,64,S] hi/lo
    vsplit_t<<<dim3(SEQL / 64, NB * NH), 256>>>();

    // 4: flash attention (writes hi/lo attn-out directly)
    flash_mma<<<dim3(SEQL / 128, NB * NH), 256, FL_SMEM>>>();

    // 5: output projection
    gemm_bf16x2<<<dim3(8, 32), 256, GEMM_SMEM>>>(ah, al, wh + 3 * (size_t)DM * DM,
                                                 wl + 3 * (size_t)DM * DM, out, 1024);
}

// round 10
// speedup vs baseline: 2.3484x; 1.0489x over previous
#include <cuda_runtime.h>
#include <cuda_bf16.h>
#include <cstdint>

#define DM   1024
#define SEQL 2048
#define NB   2
#define NH   16
#define HD   64
#define NTOK 4096   // NB*SEQL

// ------------------------- scratch (device globals) -------------------------
__device__ float g_qkv[NTOK * 3 * DM];                          // fused QKV out
__device__ __nv_bfloat16 g_xh[NTOK * DM], g_xl[NTOK * DM];      // x split
__device__ __nv_bfloat16 g_wh[4 * DM * DM], g_wl[4 * DM * DM];  // Wq,Wk,Wv,Wo split
__device__ __nv_bfloat16 g_ah[NTOK * DM], g_al[NTOK * DM];      // attn-out split
__device__ __nv_bfloat16 g_qrh[NTOK * DM], g_qrl[NTOK * DM];    // RoPE'd Q [B,H,S,64]
__device__ __nv_bfloat16 g_krh[NTOK * DM], g_krl[NTOK * DM];    // RoPE'd K [B,H,S,64]
__device__ __nv_bfloat16 g_vth[NTOK * DM], g_vtl[NTOK * DM];    // V^T [B,H,64,S]

// ------------------------------ PTX helpers --------------------------------
__device__ __forceinline__ uint32_t smem_u32(const void* p) {
    uint32_t a;
    asm("{ .reg .u64 t; cvta.to.shared.u64 t, %1; cvt.u32.u64 %0, t; }"
        : "=r"(a) : "l"(p));
    return a;
}
__device__ __forceinline__ void cpa16(uint32_t dst, const void* src) {
    asm volatile("cp.async.cg.shared.global [%0], [%1], 16;\n" :: "r"(dst), "l"(src));
}
#define CP_COMMIT() asm volatile("cp.async.commit_group;\n" ::: "memory")

__device__ __forceinline__ void ldsm4(uint32_t* r, uint32_t addr) {
    asm volatile("ldmatrix.sync.aligned.m8n8.x4.shared.b16 {%0,%1,%2,%3}, [%4];"
                 : "=r"(r[0]), "=r"(r[1]), "=r"(r[2]), "=r"(r[3]) : "r"(addr));
}
__device__ __forceinline__ void mma_bf16(float* d, const uint32_t* a, const uint32_t* b) {
    asm volatile("mma.sync.aligned.m16n8k16.row.col.f32.bf16.bf16.f32 "
                 "{%0,%1,%2,%3}, {%4,%5,%6,%7}, {%8,%9}, {%0,%1,%2,%3};"
                 : "+f"(d[0]), "+f"(d[1]), "+f"(d[2]), "+f"(d[3])
                 : "r"(a[0]), "r"(a[1]), "r"(a[2]), "r"(a[3]), "r"(b[0]), "r"(b[1]));
}

// FMA-pipe 2^x for x <= 0 (clamped), ~1e-6 accuracy
__device__ __forceinline__ float fexp2(float x) {
    x = fmaxf(x, -126.f);
    float fl = floorf(x);
    float f  = x - fl;
    float p = 1.54035304e-4f;
    p = fmaf(p, f, 1.33335581e-3f);
    p = fmaf(p, f, 9.61812911e-3f);
    p = fmaf(p, f, 5.55041087e-2f);
    p = fmaf(p, f, 2.40226507e-1f);
    p = fmaf(p, f, 6.93147180e-1f);
    p = fmaf(p, f, 1.0f);
    int e = (int)fl;
    return p * __int_as_float((e + 127) << 23);
}

__device__ __forceinline__ uint32_t pk2(float a, float b) {
    __nv_bfloat162 t = __floats2bfloat162_rn(a, b);
    return *(uint32_t*)&t;
}
__device__ __forceinline__ void split2(float a, float b, uint32_t& h, uint32_t& l) {
    __nv_bfloat16 ah = __float2bfloat16(a), bh = __float2bfloat16(b);
    h = pk2((float)ah, (float)bh);
    l = pk2(a - (float)ah, b - (float)bh);
}

// ---------------------------------------------------------------------------
// Fused fp32 -> (hi, lo) bf16 split: x (4M elems) + 4 weights (1M each)
// ---------------------------------------------------------------------------
__global__ __launch_bounds__(256) void split_all(const float* __restrict__ x,
                                                 const float* __restrict__ W0,
                                                 const float* __restrict__ W1,
                                                 const float* __restrict__ W2,
                                                 const float* __restrict__ W3) {
    int bid = blockIdx.x;
    const float* src;
    __nv_bfloat16 *dh, *dl;
    int off;
    if (bid < 16384) {                 // x
        src = x; dh = g_xh; dl = g_xl;
        off = bid * 256 + threadIdx.x;
    } else {
        int w = (bid - 16384) >> 12;   // 0..3
        const float* Ws[4] = {W0, W1, W2, W3};
        src = Ws[w];
        dh = g_wh + (size_t)w * DM * DM;
        dl = g_wl + (size_t)w * DM * DM;
        off = ((bid - 16384) & 4095) * 256 + threadIdx.x;
    }
    float v = src[off];
    __nv_bfloat16 hb = __float2bfloat16(v);
    dh[off] = hb;
    dl[off] = __float2bfloat16(v - __bfloat162float(hb));
}

// ---------------------------------------------------------------------------
// mma.sync split-bf16 GEMM: C[M,ldc] = A[M,K] * B[N,K]^T  (ldc = N total)
// Term-major MMA issue: same-acc MMAs are 8 issues apart (covers HMMA latency)
// ---------------------------------------------------------------------------
#define LDA 40
#define MAT_BYTES (128 * LDA * 2)
#define STAGE_BYTES (4 * MAT_BYTES)
#define GEMM_SMEM (2 * STAGE_BYTES)
#define NCH (DM / 32)

__device__ __forceinline__ void load_stage(const __nv_bfloat16* Ah, const __nv_bfloat16* Al,
                                           const __nv_bfloat16* Bh, const __nv_bfloat16* Bl,
                                           uint32_t sbase, int m0, int n0, int k0, int tid) {
#pragma unroll
    for (int l = 0; l < 2; l++) {
        int f   = tid + l * 256;
        int r   = f >> 2;
        int cb  = (f & 3) << 4;
        int ce  = (f & 3) << 3;
        uint32_t d = sbase + r * (LDA * 2) + cb;
        size_t offA = (size_t)(m0 + r) * DM + k0 + ce;
        size_t offB = (size_t)(n0 + r) * DM + k0 + ce;
        cpa16(d,                 Ah + offA);
        cpa16(d + MAT_BYTES,     Al + offA);
        cpa16(d + 2 * MAT_BYTES, Bh + offB);
        cpa16(d + 3 * MAT_BYTES, Bl + offB);
    }
    CP_COMMIT();
}

__global__ __launch_bounds__(256, 2)
void gemm_bf16x2(const __nv_bfloat16* __restrict__ Ah, const __nv_bfloat16* __restrict__ Al,
                 const __nv_bfloat16* __restrict__ Bh, const __nv_bfloat16* __restrict__ Bl,
                 float* __restrict__ C, int ldc) {
    extern __shared__ char sm[];
    uint32_t sb = smem_u32(sm);

    const int tid  = threadIdx.x;
    const int wid  = tid >> 5;
    const int lane = tid & 31;
    const int wm   = (wid & 1) * 64;
    const int wn   = (wid >> 1) * 32;
    const int n0   = blockIdx.x * 128;
    const int m0   = blockIdx.y * 128;

    float acc[4][4][4];
#pragma unroll
    for (int i = 0; i < 4; i++)
#pragma unroll
        for (int j = 0; j < 4; j++)
#pragma unroll
            for (int c = 0; c < 4; c++) acc[i][j][c] = 0.f;

    load_stage(Ah, Al, Bh, Bl, sb, m0, n0, 0, tid);
    load_stage(Ah, Al, Bh, Bl, sb + STAGE_BYTES, m0, n0, 32, tid);

    // A frag addr: rows 16*mt + wm, ldsm4 over 16 rows x 16 cols
    const uint32_t a4 = (uint32_t)((wm + (lane & 15)) * LDA + ((lane >> 4) << 3)) * 2;
    // B frag addr (ldsm4, 2 nt at once): mat0/1 = rows wn+ntb*16+(l&7), k halves;
    // mat2/3 = rows +8
    const uint32_t b4 = (uint32_t)((wn + ((lane >> 4) << 3) + (lane & 7)) * LDA
                                   + (((lane >> 3) & 1) << 3)) * 2;

    for (int i = 0; i < NCH; i++) {
        uint32_t base = sb + (i & 1) * STAGE_BYTES;
        if (i < NCH - 2) asm volatile("cp.async.wait_group 1;\n" ::: "memory");
        else             asm volatile("cp.async.wait_group 0;\n" ::: "memory");
        __syncthreads();

        uint32_t sAh = base, sAl = base + MAT_BYTES;
        uint32_t sBh = base + 2 * MAT_BYTES, sBl = base + 3 * MAT_BYTES;

#pragma unroll
        for (int ks = 0; ks < 2; ks++) {
            const uint32_t kcb = (uint32_t)(ks * 16) * 2;   // byte offset of k-step
            // ---- B frags: 4 ldsm4 (2 nt per ldsm4) ----
            uint32_t bh[4][2], bl[4][2];
#pragma unroll
            for (int ntb = 0; ntb < 2; ntb++) {
                uint32_t t[4];
                uint32_t off = b4 + (uint32_t)(ntb * 16 * LDA) * 2 + kcb;
                ldsm4(t, sBh + off);
                bh[2 * ntb][0] = t[0]; bh[2 * ntb][1] = t[1];
                bh[2 * ntb + 1][0] = t[2]; bh[2 * ntb + 1][1] = t[3];
                ldsm4(t, sBl + off);
                bl[2 * ntb][0] = t[0]; bl[2 * ntb][1] = t[1];
                bl[2 * ntb + 1][0] = t[2]; bl[2 * ntb + 1][1] = t[3];
            }
            // ---- A mt-pairs, term-major MMA issue ----
#pragma unroll
            for (int mtb = 0; mtb < 2; mtb++) {
                uint32_t ah0[4], ah1[4], al0[4], al1[4];
                uint32_t o0 = a4 + (uint32_t)((2 * mtb) * 16 * LDA) * 2 + kcb;
                uint32_t o1 = o0 + (uint32_t)(16 * LDA) * 2;
                ldsm4(ah0, sAh + o0);
                ldsm4(ah1, sAh + o1);
                ldsm4(al0, sAl + o0);
                ldsm4(al1, sAl + o1);
                float* a0 = &acc[2 * mtb][0][0];
                float* a1 = &acc[2 * mtb + 1][0][0];
                // hh
#pragma unroll
                for (int nt = 0; nt < 4; nt++) mma_bf16(a0 + 4 * nt, ah0, bh[nt]);
#pragma unroll
                for (int nt = 0; nt < 4; nt++) mma_bf16(a1 + 4 * nt, ah1, bh[nt]);
                // hl
#pragma unroll
                for (int nt = 0; nt < 4; nt++) mma_bf16(a0 + 4 * nt, ah0, bl[nt]);
#pragma unroll
                for (int nt = 0; nt < 4; nt++) mma_bf16(a1 + 4 * nt, ah1, bl[nt]);
                // lh
#pragma unroll
                for (int nt = 0; nt < 4; nt++) mma_bf16(a0 + 4 * nt, al0, bh[nt]);
#pragma unroll
                for (int nt = 0; nt < 4; nt++) mma_bf16(a1 + 4 * nt, al1, bh[nt]);
            }
        }
        __syncthreads();
        if (i + 2 < NCH)
            load_stage(Ah, Al, Bh, Bl, base, m0, n0, (i + 2) * 32, tid);
    }

    const int er = lane >> 2;
    const int ec = (lane & 3) * 2;
#pragma unroll
    for (int mt = 0; mt < 4; mt++)
#pragma unroll
        for (int nt = 0; nt < 4; nt++) {
            int row = m0 + wm + mt * 16 + er;
            int col = n0 + wn + nt * 8 + ec;
            *(float2*)(C + (size_t)row * ldc + col) =
                make_float2(acc[mt][nt][0], acc[mt][nt][1]);
            *(float2*)(C + (size_t)(row + 8) * ldc + col) =
                make_float2(acc[mt][nt][2], acc[mt][nt][3]);
        }
}

// ---------------------------------------------------------------------------
// RoPE on q,k from g_qkv -> [B,H,S,64] hi/lo bf16
// ---------------------------------------------------------------------------
__global__ __launch_bounds__(256) void rope_kernel(const float* __restrict__ cosT,
                                                   const float* __restrict__ sinT) {
    int idx = blockIdx.x * blockDim.x + threadIdx.x;   // < NTOK*DM
    int n = idx >> 10;
    int c = idx & 1023;
    int b = n >> 11;
    int s = n & 2047;
    int h  = c >> 6;
    int dd = c & 63;

    float cs = cosT[(s << 6) + dd];
    float sn = sinT[(s << 6) + dd];

    size_t base = (size_t)n * 3072 + (h << 6);
    int rotoff = (dd < 32) ? dd + 32 : dd - 32;
    float sgn  = (dd < 32) ? -1.f : 1.f;

    float qv   = g_qkv[base + dd];
    float qrot = sgn * g_qkv[base + rotoff];
    float kv   = g_qkv[base + 1024 + dd];
    float krot = sgn * g_qkv[base + 1024 + rotoff];

    int out = ((((b << 4) + h) * SEQL + s) << 6) + dd;
    float qr = qv * cs + qrot * sn;
    float kr = kv * cs + krot * sn;
    __nv_bfloat16 qh = __float2bfloat16(qr);
    __nv_bfloat16 kh = __float2bfloat16(kr);
    g_qrh[out] = qh; g_qrl[out] = __float2bfloat16(qr - __bfloat162float(qh));
    g_krh[out] = kh; g_krl[out] = __float2bfloat16(kr - __bfloat162float(kh));
}

// ---------------------------------------------------------------------------
// V transpose + split: g_qkv v-part [B,S,H,64] -> g_vth/g_vtl [B,H,64,S]
// ---------------------------------------------------------------------------
__global__ __launch_bounds__(256) void vsplit_t() {
    __shared__ float t[64][65];
    const int tid = threadIdx.x;
    const int bh = blockIdx.y;
    const int b = bh >> 4, h = bh & 15;
    const int s0 = blockIdx.x * 64;

#pragma unroll
    for (int l = 0; l < 16; l++) {
        int f = tid + l * 256;
        int sl = f >> 6, d = f & 63;
        t[sl][d] = g_qkv[(size_t)(b * SEQL + s0 + sl) * 3072 + 2048 + (h << 6) + d];
    }
    __syncthreads();
#pragma unroll
    for (int l = 0; l < 16; l++) {
        int f = tid + l * 256;
        int d = f >> 6, sl = f & 63;
        float v = t[sl][d];
        __nv_bfloat16 hb = __float2bfloat16(v);
        size_t o = ((size_t)bh * 64 + d) * SEQL + s0 + sl;
        g_vth[o] = hb;
        g_vtl[o] = __float2bfloat16(v - __bfloat162float(hb));
    }
}

// ---------------------------------------------------------------------------
// Flash attention, double-buffered cp.async, term-major MMA issue.
// ---------------------------------------------------------------------------
#define FP 72
#define FMAT (64 * FP * 2)            // 9216 B per 64x72 bf16 matrix
#define FSTG (4 * FMAT)               // Kh|Kl|Vh|Vl = 36864
#define FQ   (2 * 128 * FP * 2)       // Qh|Ql = 36864
#define FL_SMEM (FQ + 2 * FSTG)       // 110592
#define KSC 0.18033688f               // (1/8) * log2(e)

__global__ __launch_bounds__(256) void flash_mma() {
    extern __shared__ char smc[];
    const uint32_t sQh = smem_u32(smc);
    const uint32_t sQl = sQh + 128 * FP * 2;
    const uint32_t sST = sQh + FQ;     // stage 0 base

    const int tid  = threadIdx.x;
    const int wid  = tid >> 5;
    const int lane = tid & 31;

    const int qi = blockIdx.x;
    const int bh = blockIdx.y;
    const int b  = bh >> 4;
    const int h  = bh & 15;
    const int q0 = qi * 128;

    const __nv_bfloat16* Qhg = g_qrh + ((size_t)bh * SEQL + q0) * HD;
    const __nv_bfloat16* Qlg = g_qrl + ((size_t)bh * SEQL + q0) * HD;
    const __nv_bfloat16* Khg = g_krh + (size_t)bh * SEQL * HD;
    const __nv_bfloat16* Klg = g_krl + (size_t)bh * SEQL * HD;
    const __nv_bfloat16* Vhg = g_vth + (size_t)bh * 64 * SEQL;
    const __nv_bfloat16* Vlg = g_vtl + (size_t)bh * 64 * SEQL;

    // Q load
#pragma unroll
    for (int l = 0; l < 4; l++) {
        int f = tid + l * 256;
        int r = f >> 3;
        int c = (f & 7) << 3;
        cpa16(sQh + (r * FP + c) * 2, Qhg + (size_t)r * HD + c);
        cpa16(sQl + (r * FP + c) * 2, Qlg + (size_t)r * HD + c);
    }
    CP_COMMIT();

    // tile 0 loads
    {
        uint32_t st = sST;
#pragma unroll
        for (int l = 0; l < 2; l++) {
            int f = tid + l * 256;
            int r = f >> 3;
            int c = (f & 7) << 3;
            cpa16(st + (r * FP + c) * 2,            Khg + (size_t)r * HD + c);
            cpa16(st + FMAT + (r * FP + c) * 2,     Klg + (size_t)r * HD + c);
            cpa16(st + 2 * FMAT + (r * FP + c) * 2, Vhg + (size_t)r * SEQL + c);
            cpa16(st + 3 * FMAT + (r * FP + c) * 2, Vlg + (size_t)r * SEQL + c);
        }
        CP_COMMIT();
    }

    float m0 = -1e30f, m1 = -1e30f, l0 = 0.f, l1 = 0.f;
    float o[8][4];
#pragma unroll
    for (int i = 0; i < 8; i++)
#pragma unroll
        for (int c = 0; c < 4; c++) o[i][c] = 0.f;

    const int row0 = q0 + 16 * wid + (lane >> 2);
    const uint32_t aoffQ = ((16 * wid + (lane & 15)) * FP + ((lane >> 4) << 3)) * 2;
    const uint32_t roffB = ((lane & 15) * FP + ((lane >> 4) << 3)) * 2;

    const int nkt = 2 * qi + 2;
    for (int kt = 0; kt < nkt; kt++) {
        asm volatile("cp.async.wait_group 0;\n" ::: "memory");
        __syncthreads();

        // prefetch tile kt+1 into other buffer
        if (kt + 1 < nkt) {
            const int kn = (kt + 1) * 64;
            uint32_t st = sST + ((kt + 1) & 1) * FSTG;
#pragma unroll
            for (int l = 0; l < 2; l++) {
                int f = tid + l * 256;
                int r = f >> 3;
                int c = (f & 7) << 3;
                cpa16(st + (r * FP + c) * 2,            Khg + (size_t)(kn + r) * HD + c);
                cpa16(st + FMAT + (r * FP + c) * 2,     Klg + (size_t)(kn + r) * HD + c);
                cpa16(st + 2 * FMAT + (r * FP + c) * 2, Vhg + (size_t)r * SEQL + kn + c);
                cpa16(st + 3 * FMAT + (r * FP + c) * 2, Vlg + (size_t)r * SEQL + kn + c);
            }
            CP_COMMIT();
        }

        const int k0 = kt * 64;
        const uint32_t st = sST + (kt & 1) * FSTG;
        const uint32_t sKh = st, sKl = st + FMAT;
        const uint32_t sVh = st + 2 * FMAT, sVl = st + 3 * FMAT;

        // ---- S = Q K^T (term-major, acc distance 4) ----
        float s4[8][4];
#pragma unroll
        for (int i = 0; i < 8; i++)
#pragma unroll
            for (int c = 0; c < 4; c++) s4[i][c] = 0.f;

#pragma unroll
        for (int kc = 0; kc < 4; kc++) {
            uint32_t ah[4], al[4];
            ldsm4(ah, sQh + aoffQ + kc * 32);
            ldsm4(al, sQl + aoffQ + kc * 32);
#pragma unroll
            for (int pb = 0; pb < 2; pb++) {
                uint32_t off0 = roffB + (2 * pb) * 16 * FP * 2 + kc * 32;
                uint32_t off1 = off0 + 16 * FP * 2;
                uint32_t rh0[4], rh1[4], rl0[4], rl1[4];
                ldsm4(rh0, sKh + off0);
                ldsm4(rh1, sKh + off1);
                ldsm4(rl0, sKl + off0);
                ldsm4(rl1, sKl + off1);
                uint32_t b00h[2] = {rh0[0], rh0[2]}, b01h[2] = {rh0[1], rh0[3]};
                uint32_t b10h[2] = {rh1[0], rh1[2]}, b11h[2] = {rh1[1], rh1[3]};
                uint32_t b00l[2] = {rl0[0], rl0[2]}, b01l[2] = {rl0[1], rl0[3]};
                uint32_t b10l[2] = {rl1[0], rl1[2]}, b11l[2] = {rl1[1], rl1[3]};
                float* s = &s4[4 * pb][0];
                // hh
                mma_bf16(s + 0,  ah, b00h); mma_bf16(s + 4,  ah, b01h);
                mma_bf16(s + 8,  ah, b10h); mma_bf16(s + 12, ah, b11h);
                // hl
                mma_bf16(s + 0,  ah, b00l); mma_bf16(s + 4,  ah, b01l);
                mma_bf16(s + 8,  ah, b10l); mma_bf16(s + 12, ah, b11l);
                // lh
                mma_bf16(s + 0,  al, b00h); mma_bf16(s + 4,  al, b01h);
                mma_bf16(s + 8,  al, b10h); mma_bf16(s + 12, al, b11h);
            }
        }

        // ---- scale + mask ----
        const bool masked = (k0 + 63 >= q0);
#pragma unroll
        for (int nt = 0; nt < 8; nt++)
#pragma unroll
            for (int c = 0; c < 4; c++) {
                float sv = s4[nt][c] * KSC;
                if (masked) {
                    int col = k0 + nt * 8 + (lane & 3) * 2 + (c & 1);
                    int row = row0 + ((c >> 1) << 3);
                    if (col > row) sv = -1e30f;
                }
                s4[nt][c] = sv;
            }

        // ---- online softmax (base-2) ----
        float mx0 = -1e30f, mx1 = -1e30f;
#pragma unroll
        for (int nt = 0; nt < 8; nt++) {
            mx0 = fmaxf(mx0, fmaxf(s4[nt][0], s4[nt][1]));
            mx1 = fmaxf(mx1, fmaxf(s4[nt][2], s4[nt][3]));
        }
        mx0 = fmaxf(mx0, __shfl_xor_sync(0xffffffffu, mx0, 1));
        mx0 = fmaxf(mx0, __shfl_xor_sync(0xffffffffu, mx0, 2));
        mx1 = fmaxf(mx1, __shfl_xor_sync(0xffffffffu, mx1, 1));
        mx1 = fmaxf(mx1, __shfl_xor_sync(0xffffffffu, mx1, 2));
        float mn0 = fmaxf(m0, mx0), mn1 = fmaxf(m1, mx1);
        float al0 = fexp2(m0 - mn0), al1 = fexp2(m1 - mn1);
        m0 = mn0; m1 = mn1;

        float rs0 = 0.f, rs1 = 0.f;
#pragma unroll
        for (int nt = 0; nt < 8; nt++) {
            s4[nt][0] = fexp2(s4[nt][0] - mn0);
            s4[nt][1] = fexp2(s4[nt][1] - mn0);
            s4[nt][2] = fexp2(s4[nt][2] - mn1);
            s4[nt][3] = fexp2(s4[nt][3] - mn1);
            rs0 += s4[nt][0] + s4[nt][1];
            rs1 += s4[nt][2] + s4[nt][3];
        }
        rs0 += __shfl_xor_sync(0xffffffffu, rs0, 1);
        rs0 += __shfl_xor_sync(0xffffffffu, rs0, 2);
        rs1 += __shfl_xor_sync(0xffffffffu, rs1, 1);
        rs1 += __shfl_xor_sync(0xffffffffu, rs1, 2);
        l0 = l0 * al0 + rs0;
        l1 = l1 * al1 + rs1;
#pragma unroll
        for (int nt = 0; nt < 8; nt++) {
            o[nt][0] *= al0; o[nt][1] *= al0;
            o[nt][2] *= al1; o[nt][3] *= al1;
        }

        // ---- O += P V (term-major, acc distance 4) ----
#pragma unroll
        for (int kcp = 0; kcp < 4; kcp++) {
            uint32_t aph[4], apl[4];
            split2(s4[2 * kcp][0],     s4[2 * kcp][1],     aph[0], apl[0]);
            split2(s4[2 * kcp][2],     s4[2 * kcp][3],     aph[1], apl[1]);
            split2(s4[2 * kcp + 1][0], s4[2 * kcp + 1][1], aph[2], apl[2]);
            split2(s4[2 * kcp + 1][2], s4[2 * kcp + 1][3], aph[3], apl[3]);
#pragma unroll
            for (int pb = 0; pb < 2; pb++) {
                uint32_t off0 = roffB + (2 * pb) * 16 * FP * 2 + kcp * 32;
                uint32_t off1 = off0 + 16 * FP * 2;
                uint32_t rh0[4], rh1[4], rl0[4], rl1[4];
                ldsm4(rh0, sVh + off0);
                ldsm4(rh1, sVh + off1);
                ldsm4(rl0, sVl + off0);
                ldsm4(rl1, sVl + off1);
                uint32_t b00h[2] = {rh0[0], rh0[2]}, b01h[2] = {rh0[1], rh0[3]};
                uint32_t b10h[2] = {rh1[0], rh1[2]}, b11h[2] = {rh1[1], rh1[3]};
                uint32_t b00l[2] = {rl0[0], rl0[2]}, b01l[2] = {rl0[1], rl0[3]};
                uint32_t b10l[2] = {rl1[0], rl1[2]}, b11l[2] = {rl1[1], rl1[3]};
                float* op = &o[4 * pb][0];
                // Ph*Vh
                mma_bf16(op + 0,  aph, b00h); mma_bf16(op + 4,  aph, b01h);
                mma_bf16(op + 8,  aph, b10h); mma_bf16(op + 12, aph, b11h);
                // Pl*Vh
                mma_bf16(op + 0,  apl, b00h); mma_bf16(op + 4,  apl, b01h);
                mma_bf16(op + 8,  apl, b10h); mma_bf16(op + 12, apl, b11h);
                // Ph*Vl
                mma_bf16(op + 0,  aph, b00l); mma_bf16(op + 4,  aph, b01l);
                mma_bf16(op + 8,  aph, b10l); mma_bf16(op + 12, aph, b11l);
            }
        }
    }

    // ---- epilogue: normalize, split hi/lo, store ----
    float inv0 = 1.f / l0, inv1 = 1.f / l1;
#pragma unroll
    for (int nt = 0; nt < 8; nt++) {
        int col = (h << 6) + nt * 8 + (lane & 3) * 2;
        uint32_t hi, lo;
        split2(o[nt][0] * inv0, o[nt][1] * inv0, hi, lo);
        *(uint32_t*)(g_ah + (size_t)(b * SEQL + row0) * DM + col) = hi;
        *(uint32_t*)(g_al + (size_t)(b * SEQL + row0) * DM + col) = lo;
        split2(o[nt][2] * inv1, o[nt][3] * inv1, hi, lo);
        *(uint32_t*)(g_ah + (size_t)(b * SEQL + row0 + 8) * DM + col) = hi;
        *(uint32_t*)(g_al + (size_t)(b * SEQL + row0 + 8) * DM + col) = lo;
    }
}

// ---------------------------------------------------------------------------
extern "C" void kernel_launch(void* const* d_in, const int* in_sizes, int n_in,
                              void* d_out, int out_size) {
    const float* x    = (const float*)d_in[0];
    const float* cosT = (const float*)d_in[1];
    const float* sinT = (const float*)d_in[2];
    float* out = (float*)d_out;

    float* qkvp;
    cudaGetSymbolAddress((void**)&qkvp, g_qkv);
    __nv_bfloat16 *xh, *xl, *wh, *wl, *ah, *al;
    cudaGetSymbolAddress((void**)&xh, g_xh);
    cudaGetSymbolAddress((void**)&xl, g_xl);
    cudaGetSymbolAddress((void**)&wh, g_wh);
    cudaGetSymbolAddress((void**)&wl, g_wl);
    cudaGetSymbolAddress((void**)&ah, g_ah);
    cudaGetSymbolAddress((void**)&al, g_al);

    cudaFuncSetAttribute(gemm_bf16x2,
                         cudaFuncAttributeMaxDynamicSharedMemorySize, GEMM_SMEM);
    cudaFuncSetAttribute(flash_mma,
                         cudaFuncAttributeMaxDynamicSharedMemorySize, FL_SMEM);

    split_all<<<32768, 256>>>(x, (const float*)d_in[3], (const float*)d_in[4],
                              (const float*)d_in[5], (const float*)d_in[6]);

    gemm_bf16x2<<<dim3(24, 32), 256, GEMM_SMEM>>>(xh, xl, wh, wl, qkvp, 3072);

    rope_kernel<<<(NTOK * DM) / 256, 256>>>(cosT, sinT);

    vsplit_t<<<dim3(SEQL / 64, NB * NH), 256>>>();

    flash_mma<<<dim3(SEQL / 128, NB * NH), 256, FL_SMEM>>>();

    gemm_bf16x2<<<dim3(8, 32), 256, GEMM_SMEM>>>(ah, al, wh + 3 * (size_t)DM * DM,
                                                 wl + 3 * (size_t)DM * DM, out, 1024);
}

// round 11
// speedup vs baseline: 3.0460x; 1.2970x over previous
#include <cuda_runtime.h>
#include <cuda_fp16.h>
#include <cstdint>

#define DM   1024
#define SEQL 2048
#define NB   2
#define NH   16
#define HD   64
#define NTOK 4096   // NB*SEQL

// ------------------------- scratch (device globals) -------------------------
__device__ float g_qkv[NTOK * 3 * DM];                    // fused QKV out (fp32)
__device__ __half g_xh[NTOK * DM], g_xl[NTOK * DM];       // x split (fp16 hi/lo)
__device__ __half g_wf[4 * DM * DM];                      // weights, single fp16
__device__ __half g_ah[NTOK * DM], g_al[NTOK * DM];       // attn-out split
__device__ __half g_qrh[NTOK * DM], g_qrl[NTOK * DM];     // RoPE'd Q [B,H,S,64]
__device__ __half g_krf[NTOK * DM];                       // RoPE'd K single fp16
__device__ __half g_vtf[NTOK * DM];                       // V^T single fp16 [B,H,64,S]

// ------------------------------ PTX helpers --------------------------------
__device__ __forceinline__ uint32_t smem_u32(const void* p) {
    uint32_t a;
    asm("{ .reg .u64 t; cvta.to.shared.u64 t, %1; cvt.u32.u64 %0, t; }"
        : "=r"(a) : "l"(p));
    return a;
}
__device__ __forceinline__ void cpa16(uint32_t dst, const void* src) {
    asm volatile("cp.async.cg.shared.global [%0], [%1], 16;\n" :: "r"(dst), "l"(src));
}
#define CP_COMMIT() asm volatile("cp.async.commit_group;\n" ::: "memory")

__device__ __forceinline__ void ldsm4(uint32_t* r, uint32_t addr) {
    asm volatile("ldmatrix.sync.aligned.m8n8.x4.shared.b16 {%0,%1,%2,%3}, [%4];"
                 : "=r"(r[0]), "=r"(r[1]), "=r"(r[2]), "=r"(r[3]) : "r"(addr));
}
__device__ __forceinline__ void mma_f16(float* d, const uint32_t* a, const uint32_t* b) {
    asm volatile("mma.sync.aligned.m16n8k16.row.col.f32.f16.f16.f32 "
                 "{%0,%1,%2,%3}, {%4,%5,%6,%7}, {%8,%9}, {%0,%1,%2,%3};"
                 : "+f"(d[0]), "+f"(d[1]), "+f"(d[2]), "+f"(d[3])
                 : "r"(a[0]), "r"(a[1]), "r"(a[2]), "r"(a[3]), "r"(b[0]), "r"(b[1]));
}

// FMA-pipe 2^x for x <= 0 (clamped), ~1e-6 accuracy
__device__ __forceinline__ float fexp2(float x) {
    x = fmaxf(x, -126.f);
    float fl = floorf(x);
    float f  = x - fl;
    float p = 1.54035304e-4f;
    p = fmaf(p, f, 1.33335581e-3f);
    p = fmaf(p, f, 9.61812911e-3f);
    p = fmaf(p, f, 5.55041087e-2f);
    p = fmaf(p, f, 2.40226507e-1f);
    p = fmaf(p, f, 6.93147180e-1f);
    p = fmaf(p, f, 1.0f);
    int e = (int)fl;
    return p * __int_as_float((e + 127) << 23);
}

__device__ __forceinline__ uint32_t pk2h(float a, float b) {
    __half2 t = __floats2half2_rn(a, b);
    return *(uint32_t*)&t;
}
__device__ __forceinline__ void split2h(float a, float b, uint32_t& h, uint32_t& l) {
    __half ah = __float2half_rn(a), bh = __float2half_rn(b);
    h = pk2h(__half2float(ah), __half2float(bh));   // exact re-pack
    l = pk2h(a - __half2float(ah), b - __half2float(bh));
}

// ---------------------------------------------------------------------------
// Fused split: x -> fp16 hi/lo; weights -> single fp16
// ---------------------------------------------------------------------------
__global__ __launch_bounds__(256) void split_all(const float* __restrict__ x,
                                                 const float* __restrict__ W0,
                                                 const float* __restrict__ W1,
                                                 const float* __restrict__ W2,
                                                 const float* __restrict__ W3) {
    int bid = blockIdx.x;
    if (bid < 16384) {                 // x: hi/lo split
        int off = bid * 256 + threadIdx.x;
        float v = x[off];
        __half hb = __float2half_rn(v);
        g_xh[off] = hb;
        g_xl[off] = __float2half_rn(v - __half2float(hb));
    } else {                           // weights: single fp16 rounding
        int w = (bid - 16384) >> 12;   // 0..3
        const float* Ws[4] = {W0, W1, W2, W3};
        int off = ((bid - 16384) & 4095) * 256 + threadIdx.x;
        g_wf[(size_t)w * DM * DM + off] = __float2half_rn(Ws[w][off]);
    }
}

// ---------------------------------------------------------------------------
// fp16 2-term GEMM: C[M,ldc] = (Ah+Al)[M,K] * Bf[N,K]^T, fp32 accumulate.
// CTA 128x128, BK=32, 2-stage cp.async. smem mats: Ah | Al | Bf (pitch 80B).
// ---------------------------------------------------------------------------
#define LDA 40
#define MAT_BYTES (128 * LDA * 2)            // 10240
#define STAGE_BYTES (3 * MAT_BYTES)          // 30720
#define GEMM_SMEM (2 * STAGE_BYTES)          // 61440
#define NCH (DM / 32)

__device__ __forceinline__ void load_stage(const __half* Ah, const __half* Al,
                                           const __half* Bf,
                                           uint32_t sbase, int m0, int n0, int k0, int tid) {
#pragma unroll
    for (int l = 0; l < 2; l++) {
        int f   = tid + l * 256;
        int r   = f >> 2;
        int cb  = (f & 3) << 4;
        int ce  = (f & 3) << 3;
        uint32_t d = sbase + r * (LDA * 2) + cb;
        size_t offA = (size_t)(m0 + r) * DM + k0 + ce;
        size_t offB = (size_t)(n0 + r) * DM + k0 + ce;
        cpa16(d,                 Ah + offA);
        cpa16(d + MAT_BYTES,     Al + offA);
        cpa16(d + 2 * MAT_BYTES, Bf + offB);
    }
    CP_COMMIT();
}

__global__ __launch_bounds__(256, 2)
void gemm_f16x2(const __half* __restrict__ Ah, const __half* __restrict__ Al,
                const __half* __restrict__ Bf,
                float* __restrict__ C, int ldc) {
    extern __shared__ char sm[];
    uint32_t sb = smem_u32(sm);

    const int tid  = threadIdx.x;
    const int wid  = tid >> 5;
    const int lane = tid & 31;
    const int wm   = (wid & 1) * 64;
    const int wn   = (wid >> 1) * 32;
    const int n0   = blockIdx.x * 128;
    const int m0   = blockIdx.y * 128;

    float acc[4][4][4];
#pragma unroll
    for (int i = 0; i < 4; i++)
#pragma unroll
        for (int j = 0; j < 4; j++)
#pragma unroll
            for (int c = 0; c < 4; c++) acc[i][j][c] = 0.f;

    load_stage(Ah, Al, Bf, sb, m0, n0, 0, tid);
    load_stage(Ah, Al, Bf, sb + STAGE_BYTES, m0, n0, 32, tid);

    const uint32_t a4 = (uint32_t)((wm + (lane & 15)) * LDA + ((lane >> 4) << 3)) * 2;
    const uint32_t b4 = (uint32_t)((wn + ((lane >> 4) << 3) + (lane & 7)) * LDA
                                   + (((lane >> 3) & 1) << 3)) * 2;

    for (int i = 0; i < NCH; i++) {
        uint32_t base = sb + (i & 1) * STAGE_BYTES;
        if (i < NCH - 2) asm volatile("cp.async.wait_group 1;\n" ::: "memory");
        else             asm volatile("cp.async.wait_group 0;\n" ::: "memory");
        __syncthreads();

        uint32_t sAh = base, sAl = base + MAT_BYTES, sBf = base + 2 * MAT_BYTES;

#pragma unroll
        for (int ks = 0; ks < 2; ks++) {
            const uint32_t kcb = (uint32_t)(ks * 16) * 2;
            // B frags: 2 ldsm4 (2 nt each)
            uint32_t bf[4][2];
#pragma unroll
            for (int ntb = 0; ntb < 2; ntb++) {
                uint32_t t[4];
                ldsm4(t, sBf + b4 + (uint32_t)(ntb * 16 * LDA) * 2 + kcb);
                bf[2 * ntb][0] = t[0];     bf[2 * ntb][1] = t[1];
                bf[2 * ntb + 1][0] = t[2]; bf[2 * ntb + 1][1] = t[3];
            }
#pragma unroll
            for (int mtb = 0; mtb < 2; mtb++) {
                uint32_t ah0[4], ah1[4], al0[4], al1[4];
                uint32_t o0 = a4 + (uint32_t)((2 * mtb) * 16 * LDA) * 2 + kcb;
                uint32_t o1 = o0 + (uint32_t)(16 * LDA) * 2;
                ldsm4(ah0, sAh + o0);
                ldsm4(ah1, sAh + o1);
                ldsm4(al0, sAl + o0);
                ldsm4(al1, sAl + o1);
                float* a0 = &acc[2 * mtb][0][0];
                float* a1 = &acc[2 * mtb + 1][0][0];
#pragma unroll
                for (int nt = 0; nt < 4; nt++) mma_f16(a0 + 4 * nt, ah0, bf[nt]);
#pragma unroll
                for (int nt = 0; nt < 4; nt++) mma_f16(a1 + 4 * nt, ah1, bf[nt]);
#pragma unroll
                for (int nt = 0; nt < 4; nt++) mma_f16(a0 + 4 * nt, al0, bf[nt]);
#pragma unroll
                for (int nt = 0; nt < 4; nt++) mma_f16(a1 + 4 * nt, al1, bf[nt]);
            }
        }
        __syncthreads();
        if (i + 2 < NCH)
            load_stage(Ah, Al, Bf, base, m0, n0, (i + 2) * 32, tid);
    }

    const int er = lane >> 2;
    const int ec = (lane & 3) * 2;
#pragma unroll
    for (int mt = 0; mt < 4; mt++)
#pragma unroll
        for (int nt = 0; nt < 4; nt++) {
            int row = m0 + wm + mt * 16 + er;
            int col = n0 + wn + nt * 8 + ec;
            *(float2*)(C + (size_t)row * ldc + col) =
                make_float2(acc[mt][nt][0], acc[mt][nt][1]);
            *(float2*)(C + (size_t)(row + 8) * ldc + col) =
                make_float2(acc[mt][nt][2], acc[mt][nt][3]);
        }
}

// ---------------------------------------------------------------------------
// RoPE: Q -> hi/lo fp16, K -> single fp16, layout [B,H,S,64]
// ---------------------------------------------------------------------------
__global__ __launch_bounds__(256) void rope_kernel(const float* __restrict__ cosT,
                                                   const float* __restrict__ sinT) {
    int idx = blockIdx.x * blockDim.x + threadIdx.x;   // < NTOK*DM
    int n = idx >> 10;
    int c = idx & 1023;
    int b = n >> 11;
    int s = n & 2047;
    int h  = c >> 6;
    int dd = c & 63;

    float cs = cosT[(s << 6) + dd];
    float sn = sinT[(s << 6) + dd];

    size_t base = (size_t)n * 3072 + (h << 6);
    int rotoff = (dd < 32) ? dd + 32 : dd - 32;
    float sgn  = (dd < 32) ? -1.f : 1.f;

    float qv   = g_qkv[base + dd];
    float qrot = sgn * g_qkv[base + rotoff];
    float kv   = g_qkv[base + 1024 + dd];
    float krot = sgn * g_qkv[base + 1024 + rotoff];

    int out = ((((b << 4) + h) * SEQL + s) << 6) + dd;
    float qr = qv * cs + qrot * sn;
    float kr = kv * cs + krot * sn;
    __half qh = __float2half_rn(qr);
    g_qrh[out] = qh;
    g_qrl[out] = __float2half_rn(qr - __half2float(qh));
    g_krf[out] = __float2half_rn(kr);
}

// ---------------------------------------------------------------------------
// V transpose: g_qkv v-part [B,S,H,64] -> g_vtf single fp16 [B,H,64,S]
// ---------------------------------------------------------------------------
__global__ __launch_bounds__(256) void vsplit_t() {
    __shared__ float t[64][65];
    const int tid = threadIdx.x;
    const int bh = blockIdx.y;
    const int b = bh >> 4, h = bh & 15;
    const int s0 = blockIdx.x * 64;

#pragma unroll
    for (int l = 0; l < 16; l++) {
        int f = tid + l * 256;
        int sl = f >> 6, d = f & 63;
        t[sl][d] = g_qkv[(size_t)(b * SEQL + s0 + sl) * 3072 + 2048 + (h << 6) + d];
    }
    __syncthreads();
#pragma unroll
    for (int l = 0; l < 16; l++) {
        int f = tid + l * 256;
        int d = f >> 6, sl = f & 63;
        size_t o = ((size_t)bh * 64 + d) * SEQL + s0 + sl;
        g_vtf[o] = __float2half_rn(t[sl][d]);
    }
}

// ---------------------------------------------------------------------------
// Flash attention: Q split fp16, K/V single fp16, 2-term MMAs,
// double-buffered cp.async K/V^T, 1 sync per tile.
// ---------------------------------------------------------------------------
#define FP 72
#define FMAT (64 * FP * 2)            // 9216 B per 64x72 fp16 matrix
#define FSTG (2 * FMAT)               // Kf|Vf = 18432
#define FQ   (2 * 128 * FP * 2)       // Qh|Ql = 36864
#define FL_SMEM (FQ + 2 * FSTG)       // 73728
#define KSC 0.18033688f               // (1/8) * log2(e)

__global__ __launch_bounds__(256) void flash_mma() {
    extern __shared__ char smc[];
    const uint32_t sQh = smem_u32(smc);
    const uint32_t sQl = sQh + 128 * FP * 2;
    const uint32_t sST = sQh + FQ;     // stage 0 base

    const int tid  = threadIdx.x;
    const int wid  = tid >> 5;
    const int lane = tid & 31;

    const int qi = blockIdx.x;
    const int bh = blockIdx.y;
    const int b  = bh >> 4;
    const int h  = bh & 15;
    const int q0 = qi * 128;

    const __half* Qhg = g_qrh + ((size_t)bh * SEQL + q0) * HD;
    const __half* Qlg = g_qrl + ((size_t)bh * SEQL + q0) * HD;
    const __half* Kfg = g_krf + (size_t)bh * SEQL * HD;
    const __half* Vfg = g_vtf + (size_t)bh * 64 * SEQL;

    // Q load
#pragma unroll
    for (int l = 0; l < 4; l++) {
        int f = tid + l * 256;
        int r = f >> 3;
        int c = (f & 7) << 3;
        cpa16(sQh + (r * FP + c) * 2, Qhg + (size_t)r * HD + c);
        cpa16(sQl + (r * FP + c) * 2, Qlg + (size_t)r * HD + c);
    }
    CP_COMMIT();

    // tile 0 loads (Kf + Vf)
    {
        uint32_t st = sST;
#pragma unroll
        for (int l = 0; l < 2; l++) {
            int f = tid + l * 256;
            int r = f >> 3;
            int c = (f & 7) << 3;
            cpa16(st + (r * FP + c) * 2,        Kfg + (size_t)r * HD + c);
            cpa16(st + FMAT + (r * FP + c) * 2, Vfg + (size_t)r * SEQL + c);
        }
        CP_COMMIT();
    }

    float m0 = -1e30f, m1 = -1e30f, l0 = 0.f, l1 = 0.f;
    float o[8][4];
#pragma unroll
    for (int i = 0; i < 8; i++)
#pragma unroll
        for (int c = 0; c < 4; c++) o[i][c] = 0.f;

    const int row0 = q0 + 16 * wid + (lane >> 2);
    const uint32_t aoffQ = ((16 * wid + (lane & 15)) * FP + ((lane >> 4) << 3)) * 2;
    const uint32_t roffB = ((lane & 15) * FP + ((lane >> 4) << 3)) * 2;

    const int nkt = 2 * qi + 2;
    for (int kt = 0; kt < nkt; kt++) {
        asm volatile("cp.async.wait_group 0;\n" ::: "memory");
        __syncthreads();

        // prefetch tile kt+1 into other buffer
        if (kt + 1 < nkt) {
            const int kn = (kt + 1) * 64;
            uint32_t st = sST + ((kt + 1) & 1) * FSTG;
#pragma unroll
            for (int l = 0; l < 2; l++) {
                int f = tid + l * 256;
                int r = f >> 3;
                int c = (f & 7) << 3;
                cpa16(st + (r * FP + c) * 2,        Kfg + (size_t)(kn + r) * HD + c);
                cpa16(st + FMAT + (r * FP + c) * 2, Vfg + (size_t)r * SEQL + kn + c);
            }
            CP_COMMIT();
        }

        const int k0 = kt * 64;
        const uint32_t st = sST + (kt & 1) * FSTG;
        const uint32_t sKf = st, sVf = st + FMAT;

        // ---- S = Q K^T (2-term, term-major) ----
        float s4[8][4];
#pragma unroll
        for (int i = 0; i < 8; i++)
#pragma unroll
            for (int c = 0; c < 4; c++) s4[i][c] = 0.f;

#pragma unroll
        for (int kc = 0; kc < 4; kc++) {
            uint32_t qh[4], ql[4];
            ldsm4(qh, sQh + aoffQ + kc * 32);
            ldsm4(ql, sQl + aoffQ + kc * 32);
#pragma unroll
            for (int pb = 0; pb < 2; pb++) {
                uint32_t off0 = roffB + (2 * pb) * 16 * FP * 2 + kc * 32;
                uint32_t off1 = off0 + 16 * FP * 2;
                uint32_t kf0[4], kf1[4];
                ldsm4(kf0, sKf + off0);
                ldsm4(kf1, sKf + off1);
                uint32_t b00[2] = {kf0[0], kf0[2]}, b01[2] = {kf0[1], kf0[3]};
                uint32_t b10[2] = {kf1[0], kf1[2]}, b11[2] = {kf1[1], kf1[3]};
                float* s = &s4[4 * pb][0];
                // Qh terms
                mma_f16(s + 0,  qh, b00); mma_f16(s + 4,  qh, b01);
                mma_f16(s + 8,  qh, b10); mma_f16(s + 12, qh, b11);
                // Ql terms
                mma_f16(s + 0,  ql, b00); mma_f16(s + 4,  ql, b01);
                mma_f16(s + 8,  ql, b10); mma_f16(s + 12, ql, b11);
            }
        }

        // ---- scale + mask ----
        const bool masked = (k0 + 63 >= q0);
#pragma unroll
        for (int nt = 0; nt < 8; nt++)
#pragma unroll
            for (int c = 0; c < 4; c++) {
                float sv = s4[nt][c] * KSC;
                if (masked) {
                    int col = k0 + nt * 8 + (lane & 3) * 2 + (c & 1);
                    int row = row0 + ((c >> 1) << 3);
                    if (col > row) sv = -1e30f;
                }
                s4[nt][c] = sv;
            }

        // ---- online softmax (base-2) ----
        float mx0 = -1e30f, mx1 = -1e30f;
#pragma unroll
        for (int nt = 0; nt < 8; nt++) {
            mx0 = fmaxf(mx0, fmaxf(s4[nt][0], s4[nt][1]));
            mx1 = fmaxf(mx1, fmaxf(s4[nt][2], s4[nt][3]));
        }
        mx0 = fmaxf(mx0, __shfl_xor_sync(0xffffffffu, mx0, 1));
        mx0 = fmaxf(mx0, __shfl_xor_sync(0xffffffffu, mx0, 2));
        mx1 = fmaxf(mx1, __shfl_xor_sync(0xffffffffu, mx1, 1));
        mx1 = fmaxf(mx1, __shfl_xor_sync(0xffffffffu, mx1, 2));
        float mn0 = fmaxf(m0, mx0), mn1 = fmaxf(m1, mx1);
        float al0 = fexp2(m0 - mn0), al1 = fexp2(m1 - mn1);
        m0 = mn0; m1 = mn1;

        float rs0 = 0.f, rs1 = 0.f;
#pragma unroll
        for (int nt = 0; nt < 8; nt++) {
            s4[nt][0] = fexp2(s4[nt][0] - mn0);
            s4[nt][1] = fexp2(s4[nt][1] - mn0);
            s4[nt][2] = fexp2(s4[nt][2] - mn1);
            s4[nt][3] = fexp2(s4[nt][3] - mn1);
            rs0 += s4[nt][0] + s4[nt][1];
            rs1 += s4[nt][2] + s4[nt][3];
        }
        rs0 += __shfl_xor_sync(0xffffffffu, rs0, 1);
        rs0 += __shfl_xor_sync(0xffffffffu, rs0, 2);
        rs1 += __shfl_xor_sync(0xffffffffu, rs1, 1);
        rs1 += __shfl_xor_sync(0xffffffffu, rs1, 2);
        l0 = l0 * al0 + rs0;
        l1 = l1 * al1 + rs1;
#pragma unroll
        for (int nt = 0; nt < 8; nt++) {
            o[nt][0] *= al0; o[nt][1] *= al0;
            o[nt][2] *= al1; o[nt][3] *= al1;
        }

        // ---- O += P V (2-term, term-major) ----
#pragma unroll
        for (int kcp = 0; kcp < 4; kcp++) {
            uint32_t aph[4], apl[4];
            split2h(s4[2 * kcp][0],     s4[2 * kcp][1],     aph[0], apl[0]);
            split2h(s4[2 * kcp][2],     s4[2 * kcp][3],     aph[1], apl[1]);
            split2h(s4[2 * kcp + 1][0], s4[2 * kcp + 1][1], aph[2], apl[2]);
            split2h(s4[2 * kcp + 1][2], s4[2 * kcp + 1][3], aph[3], apl[3]);
#pragma unroll
            for (int pb = 0; pb < 2; pb++) {
                uint32_t off0 = roffB + (2 * pb) * 16 * FP * 2 + kcp * 32;
                uint32_t off1 = off0 + 16 * FP * 2;
                uint32_t vf0[4], vf1[4];
                ldsm4(vf0, sVf + off0);
                ldsm4(vf1, sVf + off1);
                uint32_t b00[2] = {vf0[0], vf0[2]}, b01[2] = {vf0[1], vf0[3]};
                uint32_t b10[2] = {vf1[0], vf1[2]}, b11[2] = {vf1[1], vf1[3]};
                float* op = &o[4 * pb][0];
                // Ph terms
                mma_f16(op + 0,  aph, b00); mma_f16(op + 4,  aph, b01);
                mma_f16(op + 8,  aph, b10); mma_f16(op + 12, aph, b11);
                // Pl terms
                mma_f16(op + 0,  apl, b00); mma_f16(op + 4,  apl, b01);
                mma_f16(op + 8,  apl, b10); mma_f16(op + 12, apl, b11);
            }
        }
    }

    // ---- epilogue: normalize, split hi/lo fp16, store ----
    float inv0 = 1.f / l0, inv1 = 1.f / l1;
#pragma unroll
    for (int nt = 0; nt < 8; nt++) {
        int col = (h << 6) + nt * 8 + (lane & 3) * 2;
        uint32_t hi, lo;
        split2h(o[nt][0] * inv0, o[nt][1] * inv0, hi, lo);
        *(uint32_t*)(g_ah + (size_t)(b * SEQL + row0) * DM + col) = hi;
        *(uint32_t*)(g_al + (size_t)(b * SEQL + row0) * DM + col) = lo;
        split2h(o[nt][2] * inv1, o[nt][3] * inv1, hi, lo);
        *(uint32_t*)(g_ah + (size_t)(b * SEQL + row0 + 8) * DM + col) = hi;
        *(uint32_t*)(g_al + (size_t)(b * SEQL + row0 + 8) * DM + col) = lo;
    }
}

// ---------------------------------------------------------------------------
extern "C" void kernel_launch(void* const* d_in, const int* in_sizes, int n_in,
                              void* d_out, int out_size) {
    const float* x    = (const float*)d_in[0];
    const float* cosT = (const float*)d_in[1];
    const float* sinT = (const float*)d_in[2];
    float* out = (float*)d_out;

    float* qkvp;
    cudaGetSymbolAddress((void**)&qkvp, g_qkv);
    __half *xh, *xl, *wf, *ah, *al;
    cudaGetSymbolAddress((void**)&xh, g_xh);
    cudaGetSymbolAddress((void**)&xl, g_xl);
    cudaGetSymbolAddress((void**)&wf, g_wf);
    cudaGetSymbolAddress((void**)&ah, g_ah);
    cudaGetSymbolAddress((void**)&al, g_al);

    cudaFuncSetAttribute(gemm_f16x2,
                         cudaFuncAttributeMaxDynamicSharedMemorySize, GEMM_SMEM);
    cudaFuncSetAttribute(flash_mma,
                         cudaFuncAttributeMaxDynamicSharedMemorySize, FL_SMEM);

    // 0: split x (hi/lo) + round weights (single)
    split_all<<<32768, 256>>>(x, (const float*)d_in[3], (const float*)d_in[4],
                              (const float*)d_in[5], (const float*)d_in[6]);

    // 1: fused QKV projection
    gemm_f16x2<<<dim3(24, 32), 256, GEMM_SMEM>>>(xh, xl, wf, qkvp, 3072);

    // 2: RoPE q (hi/lo), k (single)
    rope_kernel<<<(NTOK * DM) / 256, 256>>>(cosT, sinT);

    // 3: V transpose (single fp16)
    vsplit_t<<<dim3(SEQL / 64, NB * NH), 256>>>();

    // 4: flash attention
    flash_mma<<<dim3(SEQL / 128, NB * NH), 256, FL_SMEM>>>();

    // 5: output projection
    gemm_f16x2<<<dim3(8, 32), 256, GEMM_SMEM>>>(ah, al, wf + 3 * (size_t)DM * DM,
                                                out, 1024);
}

// round 15
// speedup vs baseline: 3.4668x; 1.1382x over previous
#include <cuda_runtime.h>
#include <cuda_fp16.h>
#include <cstdint>

#define DM   1024
#define SEQL 2048
#define NB   2
#define NH   16
#define HD   64
#define NTOK 4096   // NB*SEQL

// ------------------------- scratch (device globals) -------------------------
__device__ float g_qkv[NTOK * 3 * DM];                    // fused QKV out (fp32)
__device__ __half g_xh[NTOK * DM], g_xl[NTOK * DM];       // x split (fp16 hi/lo)
__device__ __half g_wf[4 * DM * DM];                      // weights, single fp16
__device__ __half g_ah[NTOK * DM], g_al[NTOK * DM];       // attn-out split
__device__ __half g_qrf[NTOK * DM];                       // RoPE'd Q single fp16
__device__ __half g_krf[NTOK * DM];                       // RoPE'd K single fp16
__device__ __half g_vtf[NTOK * DM];                       // V^T single fp16 [B,H,64,S]

// ------------------------------ PTX helpers --------------------------------
__device__ __forceinline__ uint32_t smem_u32(const void* p) {
    uint32_t a;
    asm("{ .reg .u64 t; cvta.to.shared.u64 t, %1; cvt.u32.u64 %0, t; }"
        : "=r"(a) : "l"(p));
    return a;
}
__device__ __forceinline__ void cpa16(uint32_t dst, const void* src) {
    asm volatile("cp.async.cg.shared.global [%0], [%1], 16;\n" :: "r"(dst), "l"(src));
}
#define CP_COMMIT() asm volatile("cp.async.commit_group;\n" ::: "memory")

__device__ __forceinline__ void ldsm4(uint32_t* r, uint32_t addr) {
    asm volatile("ldmatrix.sync.aligned.m8n8.x4.shared.b16 {%0,%1,%2,%3}, [%4];"
                 : "=r"(r[0]), "=r"(r[1]), "=r"(r[2]), "=r"(r[3]) : "r"(addr));
}
__device__ __forceinline__ void mma_f16(float* d, const uint32_t* a, const uint32_t* b) {
    asm volatile("mma.sync.aligned.m16n8k16.row.col.f32.f16.f16.f32 "
                 "{%0,%1,%2,%3}, {%4,%5,%6,%7}, {%8,%9}, {%0,%1,%2,%3};"
                 : "+f"(d[0]), "+f"(d[1]), "+f"(d[2]), "+f"(d[3])
                 : "r"(a[0]), "r"(a[1]), "r"(a[2]), "r"(a[3]), "r"(b[0]), "r"(b[1]));
}

// FMA-pipe 2^x for x <= 0 (clamped), ~1e-6 accuracy
__device__ __forceinline__ float fexp2(float x) {
    x = fmaxf(x, -126.f);
    float fl = floorf(x);
    float f  = x - fl;
    float p = 1.54035304e-4f;
    p = fmaf(p, f, 1.33335581e-3f);
    p = fmaf(p, f, 9.61812911e-3f);
    p = fmaf(p, f, 5.55041087e-2f);
    p = fmaf(p, f, 2.40226507e-1f);
    p = fmaf(p, f, 6.93147180e-1f);
    p = fmaf(p, f, 1.0f);
    int e = (int)fl;
    return p * __int_as_float((e + 127) << 23);
}

__device__ __forceinline__ uint32_t pk2h(float a, float b) {
    __half2 t = __floats2half2_rn(a, b);
    return *(uint32_t*)&t;
}
__device__ __forceinline__ void split2h(float a, float b, uint32_t& h, uint32_t& l) {
    __half ah = __float2half_rn(a), bh = __float2half_rn(b);
    h = pk2h(__half2float(ah), __half2float(bh));   // exact re-pack
    l = pk2h(a - __half2float(ah), b - __half2float(bh));
}

// ---------------------------------------------------------------------------
// Fused split: x -> fp16 hi/lo; weights -> single fp16
// ---------------------------------------------------------------------------
__global__ __launch_bounds__(256) void split_all(const float* __restrict__ x,
                                                 const float* __restrict__ W0,
                                                 const float* __restrict__ W1,
                                                 const float* __restrict__ W2,
                                                 const float* __restrict__ W3) {
    int bid = blockIdx.x;
    if (bid < 16384) {                 // x: hi/lo split
        int off = bid * 256 + threadIdx.x;
        float v = x[off];
        __half hb = __float2half_rn(v);
        g_xh[off] = hb;
        g_xl[off] = __float2half_rn(v - __half2float(hb));
    } else {                           // weights: single fp16 rounding
        int w = (bid - 16384) >> 12;   // 0..3
        const float* Ws[4] = {W0, W1, W2, W3};
        int off = ((bid - 16384) & 4095) * 256 + threadIdx.x;
        g_wf[(size_t)w * DM * DM + off] = __float2half_rn(Ws[w][off]);
    }
}

// ---------------------------------------------------------------------------
// fp16 2-term GEMM: C[M,ldc] = (Ah+Al)[M,K] * Bf[N,K]^T, fp32 accumulate.
// CTA 128x128, BK=32, 2-stage cp.async. smem mats: Ah | Al | Bf (pitch 80B).
// ---------------------------------------------------------------------------
#define LDA 40
#define MAT_BYTES (128 * LDA * 2)            // 10240
#define STAGE_BYTES (3 * MAT_BYTES)          // 30720
#define GEMM_SMEM (2 * STAGE_BYTES)          // 61440
#define NCH (DM / 32)

__device__ __forceinline__ void load_stage(const __half* Ah, const __half* Al,
                                           const __half* Bf,
                                           uint32_t sbase, int m0, int n0, int k0, int tid) {
#pragma unroll
    for (int l = 0; l < 2; l++) {
        int f   = tid + l * 256;
        int r   = f >> 2;
        int cb  = (f & 3) << 4;
        int ce  = (f & 3) << 3;
        uint32_t d = sbase + r * (LDA * 2) + cb;
        size_t offA = (size_t)(m0 + r) * DM + k0 + ce;
        size_t offB = (size_t)(n0 + r) * DM + k0 + ce;
        cpa16(d,                 Ah + offA);
        cpa16(d + MAT_BYTES,     Al + offA);
        cpa16(d + 2 * MAT_BYTES, Bf + offB);
    }
    CP_COMMIT();
}

__global__ __launch_bounds__(256, 2)
void gemm_f16x2(const __half* __restrict__ Ah, const __half* __restrict__ Al,
                const __half* __restrict__ Bf,
                float* __restrict__ C, int ldc) {
    extern __shared__ char sm[];
    uint32_t sb = smem_u32(sm);

    const int tid  = threadIdx.x;
    const int wid  = tid >> 5;
    const int lane = tid & 31;
    const int wm   = (wid & 1) * 64;
    const int wn   = (wid >> 1) * 32;
    const int n0   = blockIdx.x * 128;
    const int m0   = blockIdx.y * 128;

    float acc[4][4][4];
#pragma unroll
    for (int i = 0; i < 4; i++)
#pragma unroll
        for (int j = 0; j < 4; j++)
#pragma unroll
            for (int c = 0; c < 4; c++) acc[i][j][c] = 0.f;

    load_stage(Ah, Al, Bf, sb, m0, n0, 0, tid);
    load_stage(Ah, Al, Bf, sb + STAGE_BYTES, m0, n0, 32, tid);

    const uint32_t a4 = (uint32_t)((wm + (lane & 15)) * LDA + ((lane >> 4) << 3)) * 2;
    const uint32_t b4 = (uint32_t)((wn + ((lane >> 4) << 3) + (lane & 7)) * LDA
                                   + (((lane >> 3) & 1) << 3)) * 2;

    for (int i = 0; i < NCH; i++) {
        uint32_t base = sb + (i & 1) * STAGE_BYTES;
        if (i < NCH - 2) asm volatile("cp.async.wait_group 1;\n" ::: "memory");
        else             asm volatile("cp.async.wait_group 0;\n" ::: "memory");
        __syncthreads();

        uint32_t sAh = base, sAl = base + MAT_BYTES, sBf = base + 2 * MAT_BYTES;

#pragma unroll
        for (int ks = 0; ks < 2; ks++) {
            const uint32_t kcb = (uint32_t)(ks * 16) * 2;
            // B frags: 2 ldsm4 (2 nt each)
            uint32_t bf[4][2];
#pragma unroll
            for (int ntb = 0; ntb < 2; ntb++) {
                uint32_t t[4];
                ldsm4(t, sBf + b4 + (uint32_t)(ntb * 16 * LDA) * 2 + kcb);
                bf[2 * ntb][0] = t[0];     bf[2 * ntb][1] = t[1];
                bf[2 * ntb + 1][0] = t[2]; bf[2 * ntb + 1][1] = t[3];
            }
#pragma unroll
            for (int mtb = 0; mtb < 2; mtb++) {
                uint32_t ah0[4], ah1[4], al0[4], al1[4];
                uint32_t o0 = a4 + (uint32_t)((2 * mtb) * 16 * LDA) * 2 + kcb;
                uint32_t o1 = o0 + (uint32_t)(16 * LDA) * 2;
                ldsm4(ah0, sAh + o0);
                ldsm4(ah1, sAh + o1);
                ldsm4(al0, sAl + o0);
                ldsm4(al1, sAl + o1);
                float* a0 = &acc[2 * mtb][0][0];
                float* a1 = &acc[2 * mtb + 1][0][0];
#pragma unroll
                for (int nt = 0; nt < 4; nt++) mma_f16(a0 + 4 * nt, ah0, bf[nt]);
#pragma unroll
                for (int nt = 0; nt < 4; nt++) mma_f16(a1 + 4 * nt, ah1, bf[nt]);
#pragma unroll
                for (int nt = 0; nt < 4; nt++) mma_f16(a0 + 4 * nt, al0, bf[nt]);
#pragma unroll
                for (int nt = 0; nt < 4; nt++) mma_f16(a1 + 4 * nt, al1, bf[nt]);
            }
        }
        __syncthreads();
        if (i + 2 < NCH)
            load_stage(Ah, Al, Bf, base, m0, n0, (i + 2) * 32, tid);
    }

    const int er = lane >> 2;
    const int ec = (lane & 3) * 2;
#pragma unroll
    for (int mt = 0; mt < 4; mt++)
#pragma unroll
        for (int nt = 0; nt < 4; nt++) {
            int row = m0 + wm + mt * 16 + er;
            int col = n0 + wn + nt * 8 + ec;
            *(float2*)(C + (size_t)row * ldc + col) =
                make_float2(acc[mt][nt][0], acc[mt][nt][1]);
            *(float2*)(C + (size_t)(row + 8) * ldc + col) =
                make_float2(acc[mt][nt][2], acc[mt][nt][3]);
        }
}

// ---------------------------------------------------------------------------
// RoPE: Q, K -> single fp16, layout [B,H,S,64]
// ---------------------------------------------------------------------------
__global__ __launch_bounds__(256) void rope_kernel(const float* __restrict__ cosT,
                                                   const float* __restrict__ sinT) {
    int idx = blockIdx.x * blockDim.x + threadIdx.x;   // < NTOK*DM
    int n = idx >> 10;
    int c = idx & 1023;
    int b = n >> 11;
    int s = n & 2047;
    int h  = c >> 6;
    int dd = c & 63;

    float cs = cosT[(s << 6) + dd];
    float sn = sinT[(s << 6) + dd];

    size_t base = (size_t)n * 3072 + (h << 6);
    int rotoff = (dd < 32) ? dd + 32 : dd - 32;
    float sgn  = (dd < 32) ? -1.f : 1.f;

    float qv   = g_qkv[base + dd];
    float qrot = sgn * g_qkv[base + rotoff];
    float kv   = g_qkv[base + 1024 + dd];
    float krot = sgn * g_qkv[base + 1024 + rotoff];

    int out = ((((b << 4) + h) * SEQL + s) << 6) + dd;
    g_qrf[out] = __float2half_rn(qv * cs + qrot * sn);
    g_krf[out] = __float2half_rn(kv * cs + krot * sn);
}

// ---------------------------------------------------------------------------
// V transpose: g_qkv v-part [B,S,H,64] -> g_vtf single fp16 [B,H,64,S]
// ---------------------------------------------------------------------------
__global__ __launch_bounds__(256) void vsplit_t() {
    __shared__ float t[64][65];
    const int tid = threadIdx.x;
    const int bh = blockIdx.y;
    const int b = bh >> 4, h = bh & 15;
    const int s0 = blockIdx.x * 64;

#pragma unroll
    for (int l = 0; l < 16; l++) {
        int f = tid + l * 256;
        int sl = f >> 6, d = f & 63;
        t[sl][d] = g_qkv[(size_t)(b * SEQL + s0 + sl) * 3072 + 2048 + (h << 6) + d];
    }
    __syncthreads();
#pragma unroll
    for (int l = 0; l < 16; l++) {
        int f = tid + l * 256;
        int d = f >> 6, sl = f & 63;
        size_t o = ((size_t)bh * 64 + d) * SEQL + s0 + sl;
        g_vtf[o] = __float2half_rn(t[sl][d]);
    }
}

// ---------------------------------------------------------------------------
// Flash attention: single-term fp16 QK^T and PV, fp32 accumulate.
// Double-buffered cp.async K/V^T, 1 sync per tile.
// ---------------------------------------------------------------------------
#define FP 72
#define FMAT (64 * FP * 2)            // 9216 B per 64x72 fp16 matrix
#define FSTG (2 * FMAT)               // Kf|Vf = 18432
#define FQ   (128 * FP * 2)           // Qf = 18432
#define FL_SMEM (FQ + 2 * FSTG)       // 55296
#define KSC 0.18033688f               // (1/8) * log2(e)

__global__ __launch_bounds__(256) void flash_mma() {
    extern __shared__ char smc[];
    const uint32_t sQf = smem_u32(smc);
    const uint32_t sST = sQf + FQ;     // stage 0 base

    const int tid  = threadIdx.x;
    const int wid  = tid >> 5;
    const int lane = tid & 31;

    const int qi = blockIdx.x;
    const int bh = blockIdx.y;
    const int b  = bh >> 4;
    const int h  = bh & 15;
    const int q0 = qi * 128;

    const __half* Qfg = g_qrf + ((size_t)bh * SEQL + q0) * HD;
    const __half* Kfg = g_krf + (size_t)bh * SEQL * HD;
    const __half* Vfg = g_vtf + (size_t)bh * 64 * SEQL;

    // Q load: 128 rows x 8 16B-chunks = 1024 cp.asyncs (BUGFIX: all 4 iters)
#pragma unroll
    for (int l = 0; l < 4; l++) {
        int f = tid + l * 256;        // 0..1023
        int r = f >> 3;               // row 0..127
        int c = (f & 7) << 3;         // elem col
        cpa16(sQf + (r * FP + c) * 2, Qfg + (size_t)r * HD + c);
    }
    // tile 0 loads (Kf + Vf)
    {
        uint32_t st = sST;
#pragma unroll
        for (int l = 0; l < 2; l++) {
            int f = tid + l * 256;
            int r = f >> 3;
            int c = (f & 7) << 3;
            cpa16(st + (r * FP + c) * 2,        Kfg + (size_t)r * HD + c);
            cpa16(st + FMAT + (r * FP + c) * 2, Vfg + (size_t)r * SEQL + c);
        }
        CP_COMMIT();
    }

    float m0 = -1e30f, m1 = -1e30f, l0 = 0.f, l1 = 0.f;
    float o[8][4];
#pragma unroll
    for (int i = 0; i < 8; i++)
#pragma unroll
        for (int c = 0; c < 4; c++) o[i][c] = 0.f;

    const int row0 = q0 + 16 * wid + (lane >> 2);
    const uint32_t aoffQ = ((16 * wid + (lane & 15)) * FP + ((lane >> 4) << 3)) * 2;
    const uint32_t roffB = ((lane & 15) * FP + ((lane >> 4) << 3)) * 2;

    const int nkt = 2 * qi + 2;
    for (int kt = 0; kt < nkt; kt++) {
        asm volatile("cp.async.wait_group 0;\n" ::: "memory");
        __syncthreads();

        // prefetch tile kt+1 into other buffer
        if (kt + 1 < nkt) {
            const int kn = (kt + 1) * 64;
            uint32_t st = sST + ((kt + 1) & 1) * FSTG;
#pragma unroll
            for (int l = 0; l < 2; l++) {
                int f = tid + l * 256;
                int r = f >> 3;
                int c = (f & 7) << 3;
                cpa16(st + (r * FP + c) * 2,        Kfg + (size_t)(kn + r) * HD + c);
                cpa16(st + FMAT + (r * FP + c) * 2, Vfg + (size_t)r * SEQL + kn + c);
            }
            CP_COMMIT();
        }

        const int k0 = kt * 64;
        const uint32_t st = sST + (kt & 1) * FSTG;
        const uint32_t sKf = st, sVf = st + FMAT;

        // ---- S = Q K^T (single term) ----
        float s4[8][4];
#pragma unroll
        for (int i = 0; i < 8; i++)
#pragma unroll
            for (int c = 0; c < 4; c++) s4[i][c] = 0.f;

#pragma unroll
        for (int kc = 0; kc < 4; kc++) {
            uint32_t qf[4];
            ldsm4(qf, sQf + aoffQ + kc * 32);
#pragma unroll
            for (int pb = 0; pb < 2; pb++) {
                uint32_t off0 = roffB + (2 * pb) * 16 * FP * 2 + kc * 32;
                uint32_t off1 = off0 + 16 * FP * 2;
                uint32_t kf0[4], kf1[4];
                ldsm4(kf0, sKf + off0);
                ldsm4(kf1, sKf + off1);
                uint32_t b00[2] = {kf0[0], kf0[2]}, b01[2] = {kf0[1], kf0[3]};
                uint32_t b10[2] = {kf1[0], kf1[2]}, b11[2] = {kf1[1], kf1[3]};
                float* s = &s4[4 * pb][0];
                mma_f16(s + 0,  qf, b00); mma_f16(s + 4,  qf, b01);
                mma_f16(s + 8,  qf, b10); mma_f16(s + 12, qf, b11);
            }
        }

        // ---- scale + mask ----
        const bool masked = (k0 + 63 >= q0);
#pragma unroll
        for (int nt = 0; nt < 8; nt++)
#pragma unroll
            for (int c = 0; c < 4; c++) {
                float sv = s4[nt][c] * KSC;
                if (masked) {
                    int col = k0 + nt * 8 + (lane & 3) * 2 + (c & 1);
                    int row = row0 + ((c >> 1) << 3);
                    if (col > row) sv = -1e30f;
                }
                s4[nt][c] = sv;
            }

        // ---- online softmax (base-2) ----
        float mx0 = -1e30f, mx1 = -1e30f;
#pragma unroll
        for (int nt = 0; nt < 8; nt++) {
            mx0 = fmaxf(mx0, fmaxf(s4[nt][0], s4[nt][1]));
            mx1 = fmaxf(mx1, fmaxf(s4[nt][2], s4[nt][3]));
        }
        mx0 = fmaxf(mx0, __shfl_xor_sync(0xffffffffu, mx0, 1));
        mx0 = fmaxf(mx0, __shfl_xor_sync(0xffffffffu, mx0, 2));
        mx1 = fmaxf(mx1, __shfl_xor_sync(0xffffffffu, mx1, 1));
        mx1 = fmaxf(mx1, __shfl_xor_sync(0xffffffffu, mx1, 2));
        float mn0 = fmaxf(m0, mx0), mn1 = fmaxf(m1, mx1);
        float al0 = fexp2(m0 - mn0), al1 = fexp2(m1 - mn1);
        m0 = mn0; m1 = mn1;

        float rs0 = 0.f, rs1 = 0.f;
#pragma unroll
        for (int nt = 0; nt < 8; nt++) {
            s4[nt][0] = fexp2(s4[nt][0] - mn0);
            s4[nt][1] = fexp2(s4[nt][1] - mn0);
            s4[nt][2] = fexp2(s4[nt][2] - mn1);
            s4[nt][3] = fexp2(s4[nt][3] - mn1);
            rs0 += s4[nt][0] + s4[nt][1];
            rs1 += s4[nt][2] + s4[nt][3];
        }
        rs0 += __shfl_xor_sync(0xffffffffu, rs0, 1);
        rs0 += __shfl_xor_sync(0xffffffffu, rs0, 2);
        rs1 += __shfl_xor_sync(0xffffffffu, rs1, 1);
        rs1 += __shfl_xor_sync(0xffffffffu, rs1, 2);
        l0 = l0 * al0 + rs0;
        l1 = l1 * al1 + rs1;
#pragma unroll
        for (int nt = 0; nt < 8; nt++) {
            o[nt][0] *= al0; o[nt][1] *= al0;
            o[nt][2] *= al1; o[nt][3] *= al1;
        }

        // ---- O += P V (single term) ----
#pragma unroll
        for (int kcp = 0; kcp < 4; kcp++) {
            uint32_t ap[4];
            ap[0] = pk2h(s4[2 * kcp][0],     s4[2 * kcp][1]);
            ap[1] = pk2h(s4[2 * kcp][2],     s4[2 * kcp][3]);
            ap[2] = pk2h(s4[2 * kcp + 1][0], s4[2 * kcp + 1][1]);
            ap[3] = pk2h(s4[2 * kcp + 1][2], s4[2 * kcp + 1][3]);
#pragma unroll
            for (int pb = 0; pb < 2; pb++) {
                uint32_t off0 = roffB + (2 * pb) * 16 * FP * 2 + kcp * 32;
                uint32_t off1 = off0 + 16 * FP * 2;
                uint32_t vf0[4], vf1[4];
                ldsm4(vf0, sVf + off0);
                ldsm4(vf1, sVf + off1);
                uint32_t b00[2] = {vf0[0], vf0[2]}, b01[2] = {vf0[1], vf0[3]};
                uint32_t b10[2] = {vf1[0], vf1[2]}, b11[2] = {vf1[1], vf1[3]};
                float* op = &o[4 * pb][0];
                mma_f16(op + 0,  ap, b00); mma_f16(op + 4,  ap, b01);
                mma_f16(op + 8,  ap, b10); mma_f16(op + 12, ap, b11);
            }
        }
    }

    // ---- epilogue: normalize, split hi/lo fp16, store ----
    float inv0 = 1.f / l0, inv1 = 1.f / l1;
#pragma unroll
    for (int nt = 0; nt < 8; nt++) {
        int col = (h << 6) + nt * 8 + (lane & 3) * 2;
        uint32_t hi, lo;
        split2h(o[nt][0] * inv0, o[nt][1] * inv0, hi, lo);
        *(uint32_t*)(g_ah + (size_t)(b * SEQL + row0) * DM + col) = hi;
        *(uint32_t*)(g_al + (size_t)(b * SEQL + row0) * DM + col) = lo;
        split2h(o[nt][2] * inv1, o[nt][3] * inv1, hi, lo);
        *(uint32_t*)(g_ah + (size_t)(b * SEQL + row0 + 8) * DM + col) = hi;
        *(uint32_t*)(g_al + (size_t)(b * SEQL + row0 + 8) * DM + col) = lo;
    }
}

// ---------------------------------------------------------------------------
extern "C" void kernel_launch(void* const* d_in, const int* in_sizes, int n_in,
                              void* d_out, int out_size) {
    const float* x    = (const float*)d_in[0];
    const float* cosT = (const float*)d_in[1];
    const float* sinT = (const float*)d_in[2];
    float* out = (float*)d_out;

    float* qkvp;
    cudaGetSymbolAddress((void**)&qkvp, g_qkv);
    __half *xh, *xl, *wf, *ah, *al;
    cudaGetSymbolAddress((void**)&xh, g_xh);
    cudaGetSymbolAddress((void**)&xl, g_xl);
    cudaGetSymbolAddress((void**)&wf, g_wf);
    cudaGetSymbolAddress((void**)&ah, g_ah);
    cudaGetSymbolAddress((void**)&al, g_al);

    cudaFuncSetAttribute(gemm_f16x2,
                         cudaFuncAttributeMaxDynamicSharedMemorySize, GEMM_SMEM);
    cudaFuncSetAttribute(flash_mma,
                         cudaFuncAttributeMaxDynamicSharedMemorySize, FL_SMEM);

    // 0: split x (hi/lo) + round weights (single)
    split_all<<<32768, 256>>>(x, (const float*)d_in[3], (const float*)d_in[4],
                              (const float*)d_in[5], (const float*)d_in[6]);

    // 1: fused QKV projection
    gemm_f16x2<<<dim3(24, 32), 256, GEMM_SMEM>>>(xh, xl, wf, qkvp, 3072);

    // 2: RoPE q, k (single fp16)
    rope_kernel<<<(NTOK * DM) / 256, 256>>>(cosT, sinT);

    // 3: V transpose (single fp16)
    vsplit_t<<<dim3(SEQL / 64, NB * NH), 256>>>();

    // 4: flash attention
    flash_mma<<<dim3(SEQL / 128, NB * NH), 256, FL_SMEM>>>();

    // 5: output projection (attn-out 2-term for accuracy insurance)
    gemm_f16x2<<<dim3(8, 32), 256, GEMM_SMEM>>>(ah, al, wf + 3 * (size_t)DM * DM,
                                                out, 1024);
}

// round 17
// speedup vs baseline: 4.1004x; 1.1828x over previous
#include <cuda_runtime.h>
#include <cuda_fp16.h>
#include <cstdint>

#define DM   1024
#define SEQL 2048
#define NB   2
#define NH   16
#define HD   64
#define NTOK 4096   // NB*SEQL

// ------------------------- scratch (device globals) -------------------------
__device__ float g_qkv[NTOK * 3 * DM];                    // fused QKV out (fp32)
__device__ __half g_xf[NTOK * DM];                        // x single fp16
__device__ __half g_wf[4 * DM * DM];                      // weights, single fp16
__device__ __half g_ah[NTOK * DM], g_al[NTOK * DM];       // attn-out split (2-term)
__device__ __half g_qrf[NTOK * DM];                       // RoPE'd Q single fp16
__device__ __half g_krf[NTOK * DM];                       // RoPE'd K single fp16
__device__ __half g_vtf[NTOK * DM];                       // V^T single fp16 [B,H,64,S]

// ------------------------------ PTX helpers --------------------------------
__device__ __forceinline__ uint32_t smem_u32(const void* p) {
    uint32_t a;
    asm("{ .reg .u64 t; cvta.to.shared.u64 t, %1; cvt.u32.u64 %0, t; }"
        : "=r"(a) : "l"(p));
    return a;
}
__device__ __forceinline__ void cpa16(uint32_t dst, const void* src) {
    asm volatile("cp.async.cg.shared.global [%0], [%1], 16;\n" :: "r"(dst), "l"(src));
}
#define CP_COMMIT() asm volatile("cp.async.commit_group;\n" ::: "memory")

__device__ __forceinline__ void ldsm4(uint32_t* r, uint32_t addr) {
    asm volatile("ldmatrix.sync.aligned.m8n8.x4.shared.b16 {%0,%1,%2,%3}, [%4];"
                 : "=r"(r[0]), "=r"(r[1]), "=r"(r[2]), "=r"(r[3]) : "r"(addr));
}
__device__ __forceinline__ void mma_f16(float* d, const uint32_t* a, const uint32_t* b) {
    asm volatile("mma.sync.aligned.m16n8k16.row.col.f32.f16.f16.f32 "
                 "{%0,%1,%2,%3}, {%4,%5,%6,%7}, {%8,%9}, {%0,%1,%2,%3};"
                 : "+f"(d[0]), "+f"(d[1]), "+f"(d[2]), "+f"(d[3])
                 : "r"(a[0]), "r"(a[1]), "r"(a[2]), "r"(a[3]), "r"(b[0]), "r"(b[1]));
}

// FMA-pipe 2^x for x <= 0 (clamped), ~1e-6 accuracy
__device__ __forceinline__ float fexp2(float x) {
    x = fmaxf(x, -126.f);
    float fl = floorf(x);
    float f  = x - fl;
    float p = 1.54035304e-4f;
    p = fmaf(p, f, 1.33335581e-3f);
    p = fmaf(p, f, 9.61812911e-3f);
    p = fmaf(p, f, 5.55041087e-2f);
    p = fmaf(p, f, 2.40226507e-1f);
    p = fmaf(p, f, 6.93147180e-1f);
    p = fmaf(p, f, 1.0f);
    int e = (int)fl;
    return p * __int_as_float((e + 127) << 23);
}

__device__ __forceinline__ uint32_t pk2h(float a, float b) {
    __half2 t = __floats2half2_rn(a, b);
    return *(uint32_t*)&t;
}
__device__ __forceinline__ void split2h(float a, float b, uint32_t& h, uint32_t& l) {
    __half ah = __float2half_rn(a), bh = __float2half_rn(b);
    h = pk2h(__half2float(ah), __half2float(bh));   // exact re-pack
    l = pk2h(a - __half2float(ah), b - __half2float(bh));
}

// ---------------------------------------------------------------------------
// Fused split: x -> single fp16; weights -> single fp16
// ---------------------------------------------------------------------------
__global__ __launch_bounds__(256) void split_all(const float* __restrict__ x,
                                                 const float* __restrict__ W0,
                                                 const float* __restrict__ W1,
                                                 const float* __restrict__ W2,
                                                 const float* __restrict__ W3) {
    int bid = blockIdx.x;
    if (bid < 16384) {                 // x: single fp16 rounding
        int off = bid * 256 + threadIdx.x;
        g_xf[off] = __float2half_rn(x[off]);
    } else {                           // weights: single fp16 rounding
        int w = (bid - 16384) >> 12;   // 0..3
        const float* Ws[4] = {W0, W1, W2, W3};
        int off = ((bid - 16384) & 4095) * 256 + threadIdx.x;
        g_wf[(size_t)w * DM * DM + off] = __float2half_rn(Ws[w][off]);
    }
}

// ---------------------------------------------------------------------------
// fp16 GEMM, TERMS in {1,2}: C[M,ldc] = (Ah[+Al])[M,K] * Bf[N,K]^T, fp32 acc.
// CTA 128x128, BK=32, 2-stage cp.async. Stage mats: Ah [| Al] | Bf (pitch 80B).
// ---------------------------------------------------------------------------
#define LDA 40
#define MAT_BYTES (128 * LDA * 2)            // 10240
#define NCH (DM / 32)

template <int TERMS>
__device__ __forceinline__ void load_stage(const __half* Ah, const __half* Al,
                                           const __half* Bf,
                                           uint32_t sbase, int m0, int n0, int k0, int tid) {
#pragma unroll
    for (int l = 0; l < 2; l++) {
        int f   = tid + l * 256;
        int r   = f >> 2;
        int cb  = (f & 3) << 4;
        int ce  = (f & 3) << 3;
        uint32_t d = sbase + r * (LDA * 2) + cb;
        size_t offA = (size_t)(m0 + r) * DM + k0 + ce;
        size_t offB = (size_t)(n0 + r) * DM + k0 + ce;
        cpa16(d, Ah + offA);
        if (TERMS == 2) cpa16(d + MAT_BYTES, Al + offA);
        cpa16(d + TERMS * MAT_BYTES, Bf + offB);
    }
    CP_COMMIT();
}

template <int TERMS>
__global__ __launch_bounds__(256, 2)
void gemm_f16(const __half* __restrict__ Ah, const __half* __restrict__ Al,
              const __half* __restrict__ Bf,
              float* __restrict__ C, int ldc) {
    extern __shared__ char sm[];
    uint32_t sb = smem_u32(sm);
    const uint32_t stage_bytes = (TERMS + 1) * MAT_BYTES;

    const int tid  = threadIdx.x;
    const int wid  = tid >> 5;
    const int lane = tid & 31;
    const int wm   = (wid & 1) * 64;
    const int wn   = (wid >> 1) * 32;
    const int n0   = blockIdx.x * 128;
    const int m0   = blockIdx.y * 128;

    float acc[4][4][4];
#pragma unroll
    for (int i = 0; i < 4; i++)
#pragma unroll
        for (int j = 0; j < 4; j++)
#pragma unroll
            for (int c = 0; c < 4; c++) acc[i][j][c] = 0.f;

    load_stage<TERMS>(Ah, Al, Bf, sb, m0, n0, 0, tid);
    load_stage<TERMS>(Ah, Al, Bf, sb + stage_bytes, m0, n0, 32, tid);

    const uint32_t a4 = (uint32_t)((wm + (lane & 15)) * LDA + ((lane >> 4) << 3)) * 2;
    const uint32_t b4 = (uint32_t)((wn + ((lane >> 4) << 3) + (lane & 7)) * LDA
                                   + (((lane >> 3) & 1) << 3)) * 2;

    for (int i = 0; i < NCH; i++) {
        uint32_t base = sb + (i & 1) * stage_bytes;
        if (i < NCH - 2) asm volatile("cp.async.wait_group 1;\n" ::: "memory");
        else             asm volatile("cp.async.wait_group 0;\n" ::: "memory");
        __syncthreads();

        uint32_t sAh = base;
        uint32_t sAl = base + MAT_BYTES;                 // valid only if TERMS==2
        uint32_t sBf = base + TERMS * MAT_BYTES;

#pragma unroll
        for (int ks = 0; ks < 2; ks++) {
            const uint32_t kcb = (uint32_t)(ks * 16) * 2;
            // B frags: 2 ldsm4 (2 nt each)
            uint32_t bf[4][2];
#pragma unroll
            for (int ntb = 0; ntb < 2; ntb++) {
                uint32_t t[4];
                ldsm4(t, sBf + b4 + (uint32_t)(ntb * 16 * LDA) * 2 + kcb);
                bf[2 * ntb][0] = t[0];     bf[2 * ntb][1] = t[1];
                bf[2 * ntb + 1][0] = t[2]; bf[2 * ntb + 1][1] = t[3];
            }
#pragma unroll
            for (int mtb = 0; mtb < 2; mtb++) {
                uint32_t ah0[4], ah1[4];
                uint32_t o0 = a4 + (uint32_t)((2 * mtb) * 16 * LDA) * 2 + kcb;
                uint32_t o1 = o0 + (uint32_t)(16 * LDA) * 2;
                ldsm4(ah0, sAh + o0);
                ldsm4(ah1, sAh + o1);
                float* a0 = &acc[2 * mtb][0][0];
                float* a1 = &acc[2 * mtb + 1][0][0];
#pragma unroll
                for (int nt = 0; nt < 4; nt++) mma_f16(a0 + 4 * nt, ah0, bf[nt]);
#pragma unroll
                for (int nt = 0; nt < 4; nt++) mma_f16(a1 + 4 * nt, ah1, bf[nt]);
                if (TERMS == 2) {
                    uint32_t al0[4], al1[4];
                    ldsm4(al0, sAl + o0);
                    ldsm4(al1, sAl + o1);
#pragma unroll
                    for (int nt = 0; nt < 4; nt++) mma_f16(a0 + 4 * nt, al0, bf[nt]);
#pragma unroll
                    for (int nt = 0; nt < 4; nt++) mma_f16(a1 + 4 * nt, al1, bf[nt]);
                }
            }
        }
        __syncthreads();
        if (i + 2 < NCH)
            load_stage<TERMS>(Ah, Al, Bf, base, m0, n0, (i + 2) * 32, tid);
    }

    const int er = lane >> 2;
    const int ec = (lane & 3) * 2;
#pragma unroll
    for (int mt = 0; mt < 4; mt++)
#pragma unroll
        for (int nt = 0; nt < 4; nt++) {
            int row = m0 + wm + mt * 16 + er;
            int col = n0 + wn + nt * 8 + ec;
            *(float2*)(C + (size_t)row * ldc + col) =
                make_float2(acc[mt][nt][0], acc[mt][nt][1]);
            *(float2*)(C + (size_t)(row + 8) * ldc + col) =
                make_float2(acc[mt][nt][2], acc[mt][nt][3]);
        }
}

// ---------------------------------------------------------------------------
// RoPE: Q, K -> single fp16, layout [B,H,S,64]
// ---------------------------------------------------------------------------
__global__ __launch_bounds__(256) void rope_kernel(const float* __restrict__ cosT,
                                                   const float* __restrict__ sinT) {
    int idx = blockIdx.x * blockDim.x + threadIdx.x;   // < NTOK*DM
    int n = idx >> 10;
    int c = idx & 1023;
    int b = n >> 11;
    int s = n & 2047;
    int h  = c >> 6;
    int dd = c & 63;

    float cs = cosT[(s << 6) + dd];
    float sn = sinT[(s << 6) + dd];

    size_t base = (size_t)n * 3072 + (h << 6);
    int rotoff = (dd < 32) ? dd + 32 : dd - 32;
    float sgn  = (dd < 32) ? -1.f : 1.f;

    float qv   = g_qkv[base + dd];
    float qrot = sgn * g_qkv[base + rotoff];
    float kv   = g_qkv[base + 1024 + dd];
    float krot = sgn * g_qkv[base + 1024 + rotoff];

    int out = ((((b << 4) + h) * SEQL + s) << 6) + dd;
    g_qrf[out] = __float2half_rn(qv * cs + qrot * sn);
    g_krf[out] = __float2half_rn(kv * cs + krot * sn);
}

// ---------------------------------------------------------------------------
// V transpose: g_qkv v-part [B,S,H,64] -> g_vtf single fp16 [B,H,64,S]
// ---------------------------------------------------------------------------
__global__ __launch_bounds__(256) void vsplit_t() {
    __shared__ float t[64][65];
    const int tid = threadIdx.x;
    const int bh = blockIdx.y;
    const int b = bh >> 4, h = bh & 15;
    const int s0 = blockIdx.x * 64;

#pragma unroll
    for (int l = 0; l < 16; l++) {
        int f = tid + l * 256;
        int sl = f >> 6, d = f & 63;
        t[sl][d] = g_qkv[(size_t)(b * SEQL + s0 + sl) * 3072 + 2048 + (h << 6) + d];
    }
    __syncthreads();
#pragma unroll
    for (int l = 0; l < 16; l++) {
        int f = tid + l * 256;
        int d = f >> 6, sl = f & 63;
        size_t o = ((size_t)bh * 64 + d) * SEQL + s0 + sl;
        g_vtf[o] = __float2half_rn(t[sl][d]);
    }
}

// ---------------------------------------------------------------------------
// Flash attention: single-term fp16 QK^T and PV, fp32 accumulate.
// Double-buffered cp.async K/V^T, 1 sync per tile.  (verified R15)
// ---------------------------------------------------------------------------
#define FP 72
#define FMAT (64 * FP * 2)            // 9216 B per 64x72 fp16 matrix
#define FSTG (2 * FMAT)               // Kf|Vf = 18432
#define FQ   (128 * FP * 2)           // Qf = 18432
#define FL_SMEM (FQ + 2 * FSTG)       // 55296
#define KSC 0.18033688f               // (1/8) * log2(e)

__global__ __launch_bounds__(256) void flash_mma() {
    extern __shared__ char smc[];
    const uint32_t sQf = smem_u32(smc);
    const uint32_t sST = sQf + FQ;     // stage 0 base

    const int tid  = threadIdx.x;
    const int wid  = tid >> 5;
    const int lane = tid & 31;

    const int qi = blockIdx.x;
    const int bh = blockIdx.y;
    const int b  = bh >> 4;
    const int h  = bh & 15;
    const int q0 = qi * 128;

    const __half* Qfg = g_qrf + ((size_t)bh * SEQL + q0) * HD;
    const __half* Kfg = g_krf + (size_t)bh * SEQL * HD;
    const __half* Vfg = g_vtf + (size_t)bh * 64 * SEQL;

    // Q load: 128 rows x 8 16B-chunks = 1024 cp.asyncs
#pragma unroll
    for (int l = 0; l < 4; l++) {
        int f = tid + l * 256;        // 0..1023
        int r = f >> 3;               // row 0..127
        int c = (f & 7) << 3;         // elem col
        cpa16(sQf + (r * FP + c) * 2, Qfg + (size_t)r * HD + c);
    }
    // tile 0 loads (Kf + Vf)
    {
        uint32_t st = sST;
#pragma unroll
        for (int l = 0; l < 2; l++) {
            int f = tid + l * 256;
            int r = f >> 3;
            int c = (f & 7) << 3;
            cpa16(st + (r * FP + c) * 2,        Kfg + (size_t)r * HD + c);
            cpa16(st + FMAT + (r * FP + c) * 2, Vfg + (size_t)r * SEQL + c);
        }
        CP_COMMIT();
    }

    float m0 = -1e30f, m1 = -1e30f, l0 = 0.f, l1 = 0.f;
    float o[8][4];
#pragma unroll
    for (int i = 0; i < 8; i++)
#pragma unroll
        for (int c = 0; c < 4; c++) o[i][c] = 0.f;

    const int row0 = q0 + 16 * wid + (lane >> 2);
    const uint32_t aoffQ = ((16 * wid + (lane & 15)) * FP + ((lane >> 4) << 3)) * 2;
    const uint32_t roffB = ((lane & 15) * FP + ((lane >> 4) << 3)) * 2;

    const int nkt = 2 * qi + 2;
    for (int kt = 0; kt < nkt; kt++) {
        asm volatile("cp.async.wait_group 0;\n" ::: "memory");
        __syncthreads();

        // prefetch tile kt+1 into other buffer
        if (kt + 1 < nkt) {
            const int kn = (kt + 1) * 64;
            uint32_t st = sST + ((kt + 1) & 1) * FSTG;
#pragma unroll
            for (int l = 0; l < 2; l++) {
                int f = tid + l * 256;
                int r = f >> 3;
                int c = (f & 7) << 3;
                cpa16(st + (r * FP + c) * 2,        Kfg + (size_t)(kn + r) * HD + c);
                cpa16(st + FMAT + (r * FP + c) * 2, Vfg + (size_t)r * SEQL + kn + c);
            }
            CP_COMMIT();
        }

        const int k0 = kt * 64;
        const uint32_t st = sST + (kt & 1) * FSTG;
        const uint32_t sKf = st, sVf = st + FMAT;

        // ---- S = Q K^T (single term) ----
        float s4[8][4];
#pragma unroll
        for (int i = 0; i < 8; i++)
#pragma unroll
            for (int c = 0; c < 4; c++) s4[i][c] = 0.f;

#pragma unroll
        for (int kc = 0; kc < 4; kc++) {
            uint32_t qf[4];
            ldsm4(qf, sQf + aoffQ + kc * 32);
#pragma unroll
            for (int pb = 0; pb < 2; pb++) {
                uint32_t off0 = roffB + (2 * pb) * 16 * FP * 2 + kc * 32;
                uint32_t off1 = off0 + 16 * FP * 2;
                uint32_t kf0[4], kf1[4];
                ldsm4(kf0, sKf + off0);
                ldsm4(kf1, sKf + off1);
                uint32_t b00[2] = {kf0[0], kf0[2]}, b01[2] = {kf0[1], kf0[3]};
                uint32_t b10[2] = {kf1[0], kf1[2]}, b11[2] = {kf1[1], kf1[3]};
                float* s = &s4[4 * pb][0];
                mma_f16(s + 0,  qf, b00); mma_f16(s + 4,  qf, b01);
                mma_f16(s + 8,  qf, b10); mma_f16(s + 12, qf, b11);
            }
        }

        // ---- scale + mask ----
        const bool masked = (k0 + 63 >= q0);
#pragma unroll
        for (int nt = 0; nt < 8; nt++)
#pragma unroll
            for (int c = 0; c < 4; c++) {
                float sv = s4[nt][c] * KSC;
                if (masked) {
                    int col = k0 + nt * 8 + (lane & 3) * 2 + (c & 1);
                    int row = row0 + ((c >> 1) << 3);
                    if (col > row) sv = -1e30f;
                }
                s4[nt][c] = sv;
            }

        // ---- online softmax (base-2) ----
        float mx0 = -1e30f, mx1 = -1e30f;
#pragma unroll
        for (int nt = 0; nt < 8; nt++) {
            mx0 = fmaxf(mx0, fmaxf(s4[nt][0], s4[nt][1]));
            mx1 = fmaxf(mx1, fmaxf(s4[nt][2], s4[nt][3]));
        }
        mx0 = fmaxf(mx0, __shfl_xor_sync(0xffffffffu, mx0, 1));
        mx0 = fmaxf(mx0, __shfl_xor_sync(0xffffffffu, mx0, 2));
        mx1 = fmaxf(mx1, __shfl_xor_sync(0xffffffffu, mx1, 1));
        mx1 = fmaxf(mx1, __shfl_xor_sync(0xffffffffu, mx1, 2));
        float mn0 = fmaxf(m0, mx0), mn1 = fmaxf(m1, mx1);
        float al0 = fexp2(m0 - mn0), al1 = fexp2(m1 - mn1);
        m0 = mn0; m1 = mn1;

        float rs0 = 0.f, rs1 = 0.f;
#pragma unroll
        for (int nt = 0; nt < 8; nt++) {
            s4[nt][0] = fexp2(s4[nt][0] - mn0);
            s4[nt][1] = fexp2(s4[nt][1] - mn0);
            s4[nt][2] = fexp2(s4[nt][2] - mn1);
            s4[nt][3] = fexp2(s4[nt][3] - mn1);
            rs0 += s4[nt][0] + s4[nt][1];
            rs1 += s4[nt][2] + s4[nt][3];
        }
        rs0 += __shfl_xor_sync(0xffffffffu, rs0, 1);
        rs0 += __shfl_xor_sync(0xffffffffu, rs0, 2);
        rs1 += __shfl_xor_sync(0xffffffffu, rs1, 1);
        rs1 += __shfl_xor_sync(0xffffffffu, rs1, 2);
        l0 = l0 * al0 + rs0;
        l1 = l1 * al1 + rs1;
#pragma unroll
        for (int nt = 0; nt < 8; nt++) {
            o[nt][0] *= al0; o[nt][1] *= al0;
            o[nt][2] *= al1; o[nt][3] *= al1;
        }

        // ---- O += P V (single term) ----
#pragma unroll
        for (int kcp = 0; kcp < 4; kcp++) {
            uint32_t ap[4];
            ap[0] = pk2h(s4[2 * kcp][0],     s4[2 * kcp][1]);
            ap[1] = pk2h(s4[2 * kcp][2],     s4[2 * kcp][3]);
            ap[2] = pk2h(s4[2 * kcp + 1][0], s4[2 * kcp + 1][1]);
            ap[3] = pk2h(s4[2 * kcp + 1][2], s4[2 * kcp + 1][3]);
#pragma unroll
            for (int pb = 0; pb < 2; pb++) {
                uint32_t off0 = roffB + (2 * pb) * 16 * FP * 2 + kcp * 32;
                uint32_t off1 = off0 + 16 * FP * 2;
                uint32_t vf0[4], vf1[4];
                ldsm4(vf0, sVf + off0);
                ldsm4(vf1, sVf + off1);
                uint32_t b00[2] = {vf0[0], vf0[2]}, b01[2] = {vf0[1], vf0[3]};
                uint32_t b10[2] = {vf1[0], vf1[2]}, b11[2] = {vf1[1], vf1[3]};
                float* op = &o[4 * pb][0];
                mma_f16(op + 0,  ap, b00); mma_f16(op + 4,  ap, b01);
                mma_f16(op + 8,  ap, b10); mma_f16(op + 12, ap, b11);
            }
        }
    }

    // ---- epilogue: normalize, split hi/lo fp16, store ----
    float inv0 = 1.f / l0, inv1 = 1.f / l1;
#pragma unroll
    for (int nt = 0; nt < 8; nt++) {
        int col = (h << 6) + nt * 8 + (lane & 3) * 2;
        uint32_t hi, lo;
        split2h(o[nt][0] * inv0, o[nt][1] * inv0, hi, lo);
        *(uint32_t*)(g_ah + (size_t)(b * SEQL + row0) * DM + col) = hi;
        *(uint32_t*)(g_al + (size_t)(b * SEQL + row0) * DM + col) = lo;
        split2h(o[nt][2] * inv1, o[nt][3] * inv1, hi, lo);
        *(uint32_t*)(g_ah + (size_t)(b * SEQL + row0 + 8) * DM + col) = hi;
        *(uint32_t*)(g_al + (size_t)(b * SEQL + row0 + 8) * DM + col) = lo;
    }
}

// ---------------------------------------------------------------------------
extern "C" void kernel_launch(void* const* d_in, const int* in_sizes, int n_in,
                              void* d_out, int out_size) {
    const float* x    = (const float*)d_in[0];
    const float* cosT = (const float*)d_in[1];
    const float* sinT = (const float*)d_in[2];
    float* out = (float*)d_out;

    float* qkvp;
    cudaGetSymbolAddress((void**)&qkvp, g_qkv);
    __half *xf, *wf, *ah, *al;
    cudaGetSymbolAddress((void**)&xf, g_xf);
    cudaGetSymbolAddress((void**)&wf, g_wf);
    cudaGetSymbolAddress((void**)&ah, g_ah);
    cudaGetSymbolAddress((void**)&al, g_al);

    const int SMEM1 = 2 * 2 * MAT_BYTES;   // 1-term: Af|Bf x2 stages = 40960
    const int SMEM2 = 2 * 3 * MAT_BYTES;   // 2-term: Ah|Al|Bf x2 stages = 61440
    cudaFuncSetAttribute(gemm_f16<1>,
                         cudaFuncAttributeMaxDynamicSharedMemorySize, SMEM1);
    cudaFuncSetAttribute(gemm_f16<2>,
                         cudaFuncAttributeMaxDynamicSharedMemorySize, SMEM2);
    cudaFuncSetAttribute(flash_mma,
                         cudaFuncAttributeMaxDynamicSharedMemorySize, FL_SMEM);

    // 0: round x + weights to fp16
    split_all<<<32768, 256>>>(x, (const float*)d_in[3], (const float*)d_in[4],
                              (const float*)d_in[5], (const float*)d_in[6]);

    // 1: fused QKV projection (single-term fp16)
    gemm_f16<1><<<dim3(24, 32), 256, SMEM1>>>(xf, nullptr, wf, qkvp, 3072);

    // 2: RoPE q, k (single fp16)
    rope_kernel<<<(NTOK * DM) / 256, 256>>>(cosT, sinT);

    // 3: V transpose (single fp16)
    vsplit_t<<<dim3(SEQL / 64, NB * NH), 256>>>();

    // 4: flash attention
    flash_mma<<<dim3(SEQL / 128, NB * NH), 256, FL_SMEM>>>();

    // 5: output projection (attn-out 2-term: accuracy buffer)
    gemm_f16<2><<<dim3(8, 32), 256, SMEM2>>>(ah, al, wf + 3 * (size_t)DM * DM,
                                             out, 1024);
}